// round 7
// baseline (speedup 1.0000x reference)
#include <cuda_runtime.h>
#include <cuda_fp16.h>
#include <math.h>

#define NUM_WIRES 18
#define BATCH     64
#define GB        32                // batch-group size (two groups: L2-resident)
#define DIM       262144            // 2^18
#define CHUNK_BITS 13
#define CHUNK     8192              // 2^13
#define NCHUNK    32                // 2^(18-13)
#define PL_THREADS 512
#define PH_THREADS 256

// Half-precision ping-pong state buffers (67MB each; both fit L2 together for
// a 32-element batch group). __device__ globals are the sanctioned scratch.
__device__ __half2 g_h0[BATCH * DIM];
__device__ __half2 g_h1[BATCH * DIM];
// Expval partials: [batch][chunk][wire]
__device__ float g_partial[BATCH * NCHUNK * NUM_WIRES];

// ---------------------------------------------------------------------------
// helpers
// ---------------------------------------------------------------------------

__device__ __forceinline__ void apply_gate(float2& a, float2& b, float4 g) {
    float ar = fmaf(g.x, a.x, -g.y * b.x);
    float ai = fmaf(g.x, a.y, -g.y * b.y);
    float br = fmaf(g.y, a.x,  g.x * b.x);
    float bi = fmaf(g.y, a.y,  g.x * b.y);
    a.x = fmaf(g.z, ar,  g.w * ai);
    a.y = fmaf(g.z, ai, -g.w * ar);
    b.x = fmaf(g.z, br, -g.w * bi);
    b.y = fmaf(g.z, bi,  g.w * br);
}

// smem XOR swizzle on float2 index (conflict-mitigating for all stage patterns)
__device__ __forceinline__ int SW(int t) { return t ^ ((t >> 4) & 63); }

// inverse Gray code (prefix-xor from MSB), valid for values < 2^16
__device__ __forceinline__ int invgray(int t) {
    t ^= t >> 1; t ^= t >> 2; t ^= t >> 4; t ^= t >> 8;
    return t;
}

__device__ __forceinline__ unsigned h2bits(__half2 h) {
    unsigned lo = __half_as_ushort(__low2half(h));
    unsigned hi = __half_as_ushort(__high2half(h));
    return lo | (hi << 16);
}
__device__ __forceinline__ float2 bits2f2(unsigned u) {
    __half2 h = __halves2half2(__ushort_as_half((unsigned short)(u & 0xFFFF)),
                               __ushort_as_half((unsigned short)(u >> 16)));
    return __half22float2(h);
}
__device__ __forceinline__ unsigned f22bits(float2 v) {
    return h2bits(__float22half2_rn(v));
}

// gate coefficients for wires [w0, w0+n) of a layer into shared memory
__device__ __forceinline__ void load_gates(float4* sg, const float* params,
                                           int layer, int w0, int n, int tid) {
    if (tid < n) {
        int w = w0 + tid;
        float ty = params[(layer * 2 + 0) * NUM_WIRES + w] * 0.5f;
        float tz = params[(layer * 2 + 1) * NUM_WIRES + w] * 0.5f;
        sg[tid] = make_float4(cosf(ty), sinf(ty), cosf(tz), sinf(tz));
    }
}

// ---------------------------------------------------------------------------
// pass_high: wires 0..4 (index bits 17..13). Register-only, in-place on half2.
// 32 amplitudes per thread strided 2^13; loads batched; fp32 compute.
// ---------------------------------------------------------------------------
__global__ void __launch_bounds__(PH_THREADS, 2)
k_pass_high(__half2* __restrict__ buf, const float* __restrict__ params, int layer) {
    __shared__ float4 sg[5];
    load_gates(sg, params, layer, 0, 5, threadIdx.x);
    __syncthreads();

    int gid = blockIdx.x * PH_THREADS + threadIdx.x;   // GB*CHUNK threads
    int b = gid >> CHUNK_BITS;
    int u = gid & (CHUNK - 1);
    __half2* p = buf + (long)b * DIM + u;

    __half2 hh[32];
#pragma unroll
    for (int r = 0; r < 32; ++r) hh[r] = p[(long)r << CHUNK_BITS];

    float2 x[32];
#pragma unroll
    for (int r = 0; r < 32; ++r) x[r] = __half22float2(hh[r]);

#pragma unroll
    for (int w = 0; w < 5; ++w) {
        float4 g = sg[w];
        int m = 16 >> w;                     // wire w <-> r-bit (4-w)
#pragma unroll
        for (int r = 0; r < 32; ++r)
            if (!(r & m)) apply_gate(x[r], x[r | m], g);
    }

#pragma unroll
    for (int r = 0; r < 32; ++r) p[(long)r << CHUNK_BITS] = __float22half2_rn(x[r]);
}

// first variant: reads separate fp32 re/im arrays, writes half2
__global__ void __launch_bounds__(PH_THREADS, 2)
k_pass_high_first(const float* __restrict__ sre,
                  const float* __restrict__ sim,
                  __half2* __restrict__ out,
                  const float* __restrict__ params) {
    __shared__ float4 sg[5];
    load_gates(sg, params, 0, 0, 5, threadIdx.x);
    __syncthreads();

    int gid = blockIdx.x * PH_THREADS + threadIdx.x;
    int b = gid >> CHUNK_BITS;
    int u = gid & (CHUNK - 1);
    long base = (long)b * DIM + u;

    float2 x[32];
#pragma unroll
    for (int r = 0; r < 32; ++r) x[r].x = sre[base + ((long)r << CHUNK_BITS)];
#pragma unroll
    for (int r = 0; r < 32; ++r) x[r].y = sim[base + ((long)r << CHUNK_BITS)];

#pragma unroll
    for (int w = 0; w < 5; ++w) {
        float4 g = sg[w];
        int m = 16 >> w;
#pragma unroll
        for (int r = 0; r < 32; ++r)
            if (!(r & m)) apply_gate(x[r], x[r | m], g);
    }
    __half2* p = out + base;
#pragma unroll
    for (int r = 0; r < 32; ++r) p[(long)r << CHUNK_BITS] = __float22half2_rn(x[r]);
}

// ---------------------------------------------------------------------------
// pass_low: wires 5..17 (bits 12..0) in 64KB fp32 shared tiles (2 CTAs/SM);
// global state is half2; then the CNOT-ladder permutation (inverse-Gray
// scatter, 8B paired stores). last==true: compute <Z_w> partials instead.
// ---------------------------------------------------------------------------
__global__ void __launch_bounds__(PL_THREADS, 2)
k_pass_low(const __half2* __restrict__ in,
           __half2* __restrict__ out,
           const float* __restrict__ params,
           float* __restrict__ partial,
           int layer, int last) {
    extern __shared__ float2 sh[];           // 2^13 float2 = 64KB
    __shared__ float4 sg[13];                // wires 5..17 -> sg[w-5]
    int tid = threadIdx.x;
    load_gates(sg, params, layer, 5, 13, tid);

    int b = blockIdx.x >> 5;
    int H = blockIdx.x & 31;                 // source chunk (bits 13..17)
    const uint4* src = (const uint4*)(in + (long)b * DIM + ((long)H << CHUNK_BITS));

    // batched fill: 4 independent 16B loads (each = 4 half2) per thread
    {
        uint4 v[4];
#pragma unroll
        for (int k = 0; k < 4; ++k) v[k] = src[tid + k * PL_THREADS];
#pragma unroll
        for (int k = 0; k < 4; ++k) {
            int t = 4 * (tid + k * PL_THREADS);
            sh[SW(t)]     = bits2f2(v[k].x);
            sh[SW(t + 1)] = bits2f2(v[k].y);
            sh[SW(t + 2)] = bits2f2(v[k].z);
            sh[SW(t + 3)] = bits2f2(v[k].w);
        }
    }
    __syncthreads();

    // stage A: bits 0..3 (wires 17..14). 512 groups of 16, 1 per thread.
    {
        int base = tid << 4;
        float2 x[16];
#pragma unroll
        for (int j = 0; j < 16; ++j) x[j] = sh[SW(base + j)];
#pragma unroll
        for (int p = 0; p < 4; ++p) {
            float4 g = sg[12 - p];           // wire 17-p
            int m = 1 << p;
#pragma unroll
            for (int j = 0; j < 16; ++j)
                if (!(j & m)) apply_gate(x[j], x[j | m], g);
        }
#pragma unroll
        for (int j = 0; j < 16; ++j) sh[SW(base + j)] = x[j];
    }
    __syncthreads();

    // stage B: bits 4..7 (wires 13..10). group = bits 0..3 x bits 8..12.
    {
        int base = (tid & 15) | ((tid >> 4) << 8);
        float2 x[16];
#pragma unroll
        for (int j = 0; j < 16; ++j) x[j] = sh[SW(base | (j << 4))];
#pragma unroll
        for (int p = 0; p < 4; ++p) {
            float4 g = sg[8 - p];            // wire 13-p
            int m = 1 << p;
#pragma unroll
            for (int j = 0; j < 16; ++j)
                if (!(j & m)) apply_gate(x[j], x[j | m], g);
        }
#pragma unroll
        for (int j = 0; j < 16; ++j) sh[SW(base | (j << 4))] = x[j];
    }
    __syncthreads();

    // stage C: bits 8..11 (wires 9..6). group = bits 0..7 x bit 12.
    {
        int base = (tid & 255) | ((tid >> 8) << 12);
        float2 x[16];
#pragma unroll
        for (int j = 0; j < 16; ++j) x[j] = sh[SW(base | (j << 8))];
#pragma unroll
        for (int p = 0; p < 4; ++p) {
            float4 g = sg[4 - p];            // wire 9-p
            int m = 1 << p;
#pragma unroll
            for (int j = 0; j < 16; ++j)
                if (!(j & m)) apply_gate(x[j], x[j | m], g);
        }
#pragma unroll
        for (int j = 0; j < 16; ++j) sh[SW(base | (j << 8))] = x[j];
    }
    __syncthreads();

    // stage D: bit 12 (wire 5). 4096 pairs, 8 per thread.
    {
        float4 g = sg[0];                    // wire 5
#pragma unroll
        for (int j = 0; j < 8; ++j) {
            int lo = tid * 8 + j;
            float2 a = sh[SW(lo)];
            float2 bb = sh[SW(lo | 4096)];
            apply_gate(a, bb, g);
            sh[SW(lo)] = a;
            sh[SW(lo | 4096)] = bb;
        }
    }
    __syncthreads();

    // CNOT-ladder permutation: dest = invgray18(src)
    int pm = (__popc(H) & 1) ? (CHUNK - 1) : 0;
    int Hd = H ^ (H >> 1); Hd ^= Hd >> 2; Hd ^= Hd >> 4;  // invgray5

    if (!last) {
        // invgray maps pair {t,t+1} (t even) to {q, q^1}: 8B paired stores
        uint2* dst = (uint2*)(out + (long)b * DIM + ((long)Hd << CHUNK_BITS));
#pragma unroll
        for (int k = 0; k < 8; ++k) {
            int t = 2 * (tid + k * PL_THREADS);
            int q = invgray(t) ^ pm;
            unsigned b0 = f22bits(sh[SW(t)]);
            unsigned b1 = f22bits(sh[SW(t + 1)]);
            uint2 o;
            o.x = (q & 1) ? b1 : b0;
            o.y = (q & 1) ? b0 : b1;
            dst[q >> 1] = o;
        }
    } else {
        float acc[NUM_WIRES];
#pragma unroll
        for (int w = 0; w < NUM_WIRES; ++w) acc[w] = 0.0f;
        int hi = Hd << CHUNK_BITS;
#pragma unroll
        for (int k = 0; k < 8; ++k) {
            int t = 2 * (tid + k * PL_THREADS);
            float2 v0 = sh[SW(t)];
            float2 v1 = sh[SW(t + 1)];
            float pr0 = v0.x * v0.x + v0.y * v0.y;
            float pr1 = v1.x * v1.x + v1.y * v1.y;
            int q = invgray(t) ^ pm;
            int d = hi | q;
            float both = pr0 + pr1;
            unsigned bb = __float_as_uint(both);
#pragma unroll
            for (int w = 0; w < 17; ++w) {
                unsigned bit = (unsigned)(d >> (17 - w)) & 1u;
                acc[w] += __uint_as_float(bb ^ (bit << 31));
            }
            float diff = pr0 - pr1;
            acc[17] += (q & 1) ? -diff : diff;
        }
#pragma unroll
        for (int w = 0; w < NUM_WIRES; ++w)
#pragma unroll
            for (int o = 16; o; o >>= 1)
                acc[w] += __shfl_down_sync(0xFFFFFFFFu, acc[w], o);
        __syncthreads();
        float* scratch = (float*)sh;
        int warp = tid >> 5, lane = tid & 31;
        if (lane == 0)
#pragma unroll
            for (int w = 0; w < NUM_WIRES; ++w) scratch[warp * NUM_WIRES + w] = acc[w];
        __syncthreads();
        if (tid < NUM_WIRES) {
            float s = 0.0f;
#pragma unroll
            for (int k = 0; k < PL_THREADS / 32; ++k) s += scratch[k * NUM_WIRES + tid];
            partial[(b * NCHUNK + H) * NUM_WIRES + tid] = s;
        }
    }
}

// ---------------------------------------------------------------------------
// head: feats @ head_w.T + head_b
// ---------------------------------------------------------------------------
__global__ void k_head(const float* __restrict__ head_w,
                       const float* __restrict__ head_b,
                       float* __restrict__ out) {
    int b = threadIdx.x;
    if (b < BATCH) {
        float s = head_b[0];
#pragma unroll
        for (int w = 0; w < NUM_WIRES; ++w) {
            float f = 0.0f;
#pragma unroll
            for (int c = 0; c < NCHUNK; ++c)
                f += g_partial[(b * NCHUNK + c) * NUM_WIRES + w];
            s = fmaf(f, head_w[w], s);
        }
        out[b] = s;
    }
}

// ---------------------------------------------------------------------------
extern "C" void kernel_launch(void* const* d_in, const int* in_sizes, int n_in,
                              void* d_out, int out_size) {
    const float* state_re = (const float*)d_in[0];
    const float* state_im = (const float*)d_in[1];
    const float* params   = (const float*)d_in[2];
    const float* head_w   = (const float*)d_in[3];
    const float* head_b   = (const float*)d_in[4];
    float* out = (float*)d_out;

    cudaFuncSetAttribute(k_pass_low, cudaFuncAttributeMaxDynamicSharedMemorySize,
                         CHUNK * (int)sizeof(float2));

    static __half2* h0p = nullptr;
    static __half2* h1p = nullptr;
    static float*   ptp = nullptr;
    if (!h0p) {
        cudaGetSymbolAddress((void**)&h0p, g_h0);
        cudaGetSymbolAddress((void**)&h1p, g_h1);
        cudaGetSymbolAddress((void**)&ptp, g_partial);
    }

    const int ph_blocks = (GB * CHUNK) / PH_THREADS;   // 1024
    const int pl_blocks = GB * NCHUNK;                 // 1024
    const int shmem = CHUNK * (int)sizeof(float2);     // 64KB

    // Process batch in L2-resident groups of GB=32 (working set 67MB < L2)
    for (int grp = 0; grp < BATCH / GB; ++grp) {
        long boff = (long)grp * GB * DIM;
        __half2* h0 = h0p + boff;
        __half2* h1 = h1p + boff;
        float* part = ptp + (long)grp * GB * NCHUNK * NUM_WIRES;

        // layer 0
        k_pass_high_first<<<ph_blocks, PH_THREADS>>>(state_re + boff, state_im + boff, h0, params);
        k_pass_low<<<pl_blocks, PL_THREADS, shmem>>>(h0, h1, params, part, 0, 0);
        // layer 1
        k_pass_high<<<ph_blocks, PH_THREADS>>>(h1, params, 1);
        k_pass_low<<<pl_blocks, PL_THREADS, shmem>>>(h1, h0, params, part, 1, 0);
        // layer 2
        k_pass_high<<<ph_blocks, PH_THREADS>>>(h0, params, 2);
        k_pass_low<<<pl_blocks, PL_THREADS, shmem>>>(h0, h1, params, part, 2, 1);
    }

    k_head<<<1, 64>>>(head_w, head_b, out);
}

// round 8
// speedup vs baseline: 1.0717x; 1.0717x over previous
#include <cuda_runtime.h>
#include <cuda_fp16.h>
#include <math.h>

#define NUM_WIRES 18
#define BATCH     64
#define NPAIR     32               // two batch states packed per f32x2 lane-pair
#define GP        16               // pairs per L2-resident group (2 groups)
#define DIM       262144           // 2^18
#define CHUNK_BITS 13
#define CHUNK     8192
#define NCHUNK    32
#define PL_THREADS 512
#define PH_THREADS 256

typedef unsigned long long u64;

// SoA component planes; each half2 = (state_s0, state_s1)
__device__ __half2 g_re0[NPAIR * DIM];
__device__ __half2 g_im0[NPAIR * DIM];
__device__ __half2 g_re1[NPAIR * DIM];
__device__ __half2 g_im1[NPAIR * DIM];
__device__ float g_partial[BATCH * NCHUNK * NUM_WIRES];

// ---- packed f32x2 primitives ----
__device__ __forceinline__ u64 pk(float lo, float hi) {
    u64 r; asm("mov.b64 %0,{%1,%2};" : "=l"(r) : "f"(lo), "f"(hi)); return r;
}
__device__ __forceinline__ u64 pk2(float x) { return pk(x, x); }
__device__ __forceinline__ float2 up(u64 v) {
    float2 f; asm("mov.b64 {%0,%1},%2;" : "=f"(f.x), "=f"(f.y) : "l"(v)); return f;
}
__device__ __forceinline__ u64 fma2(u64 a, u64 b, u64 c) {
    u64 d; asm("fma.rn.f32x2 %0,%1,%2,%3;" : "=l"(d) : "l"(a), "l"(b), "l"(c)); return d;
}
__device__ __forceinline__ u64 mul2(u64 a, u64 b) {
    u64 d; asm("mul.rn.f32x2 %0,%1,%2;" : "=l"(d) : "l"(a), "l"(b)); return d;
}
__device__ __forceinline__ u64 h2u_pk(unsigned v) {
    __half2 h; *(unsigned*)&h = v; float2 f = __half22float2(h); return pk(f.x, f.y);
}
__device__ __forceinline__ unsigned pk2hu(u64 v) {
    float2 f = up(v); __half2 h = __floats2half2_rn(f.x, f.y); return *(unsigned*)&h;
}

__device__ __forceinline__ int SW(int t) { return t ^ ((t >> 4) & 63); }
__device__ __forceinline__ int invgray(int t) {
    t ^= t >> 1; t ^= t >> 2; t ^= t >> 4; t ^= t >> 8; return t;
}

// fused RY then RZ on packed complex pair (a = bit0 branch)
__device__ __forceinline__ void gate_ryrz(u64& ar, u64& ai, u64& br, u64& bi,
                                          u64 c, u64 s, u64 ns, u64 cz, u64 sz, u64 nsz) {
    u64 nar = fma2(c, ar, mul2(ns, br));
    u64 nai = fma2(c, ai, mul2(ns, bi));
    u64 nbr = fma2(s, ar, mul2(c, br));
    u64 nbi = fma2(s, ai, mul2(c, bi));
    ar = fma2(cz, nar, mul2(sz, nai));
    ai = fma2(cz, nai, mul2(nsz, nar));
    br = fma2(cz, nbr, mul2(nsz, nbi));
    bi = fma2(cz, nbi, mul2(sz, nbr));
}
__device__ __forceinline__ void gate_ry(u64& ar, u64& ai, u64& br, u64& bi,
                                        u64 c, u64 s, u64 ns) {
    u64 nar = fma2(c, ar, mul2(ns, br));
    u64 nai = fma2(c, ai, mul2(ns, bi));
    br = fma2(s, ar, mul2(c, br));
    bi = fma2(s, ai, mul2(c, bi));
    ar = nar; ai = nai;
}
// RY on one real component (pass_high planes)
__device__ __forceinline__ void ry1(u64& a, u64& b, u64 c, u64 s, u64 ns) {
    u64 na = fma2(c, a, mul2(ns, b));
    b = fma2(s, a, mul2(c, b));
    a = na;
}
// paired scattered store: A -> dest q, B -> dest q^1
__device__ __forceinline__ void st_pair(__half2* pl, int q, u64 A, u64 B) {
    unsigned va = pk2hu(A), vb = pk2hu(B);
    uint2 o; o.x = (q & 1) ? vb : va; o.y = (q & 1) ? va : vb;
    *(uint2*)(pl + (q & ~1)) = o;
}

// ---------------------------------------------------------------------------
// pass_high: RY-only, wires 0..4 (bits 17..13), per component plane, in place.
// ---------------------------------------------------------------------------
__global__ void __launch_bounds__(PH_THREADS, 2)
k_pass_high(__half2* __restrict__ bre, __half2* __restrict__ bim,
            const float* __restrict__ params, int layer) {
    int gid = blockIdx.x * PH_THREADS + threadIdx.x;
    int u = gid & (CHUNK - 1);
    int r = gid >> CHUNK_BITS;          // 0..2*GP-1
    __half2* pl = ((r & 1) ? bim : bre) + (long)(r >> 1) * DIM + u;

    u64 x[32];
#pragma unroll
    for (int h = 0; h < 2; ++h) {
        unsigned hb[16];
#pragma unroll
        for (int j = 0; j < 16; ++j)
            hb[j] = *(const unsigned*)(pl + ((long)(h * 16 + j) << CHUNK_BITS));
#pragma unroll
        for (int j = 0; j < 16; ++j) x[h * 16 + j] = h2u_pk(hb[j]);
    }
#pragma unroll
    for (int w = 0; w < 5; ++w) {
        float ty = params[(layer * 2) * NUM_WIRES + w] * 0.5f;
        float cy = cosf(ty), sy = sinf(ty);
        u64 c = pk2(cy), s = pk2(sy), ns = pk2(-sy);
        int m = 16 >> w;
#pragma unroll
        for (int j = 0; j < 32; ++j)
            if (!(j & m)) ry1(x[j], x[j | m], c, s, ns);
    }
#pragma unroll
    for (int j = 0; j < 32; ++j)
        *(unsigned*)(pl + ((long)j << CHUNK_BITS)) = pk2hu(x[j]);
}

// layer-0 variant: fp32 inputs (rows 2p, 2p+1) -> packed half2 planes
__global__ void __launch_bounds__(PH_THREADS, 2)
k_first(const float* __restrict__ sre, const float* __restrict__ sim,
        __half2* __restrict__ ore, __half2* __restrict__ oim,
        const float* __restrict__ params) {
    int gid = blockIdx.x * PH_THREADS + threadIdx.x;
    int u = gid & (CHUNK - 1);
    int r = gid >> CHUNK_BITS;
    int c = r & 1, p = r >> 1;
    const float* src = c ? sim : sre;
    const float* r0 = src + (long)(2 * p) * DIM + u;
    const float* r1 = src + (long)(2 * p + 1) * DIM + u;

    u64 x[32];
#pragma unroll
    for (int j = 0; j < 32; ++j)
        x[j] = pk(r0[(long)j << CHUNK_BITS], r1[(long)j << CHUNK_BITS]);
#pragma unroll
    for (int w = 0; w < 5; ++w) {
        float ty = params[w] * 0.5f;
        float cy = cosf(ty), sy = sinf(ty);
        u64 cc = pk2(cy), s = pk2(sy), ns = pk2(-sy);
        int m = 16 >> w;
#pragma unroll
        for (int j = 0; j < 32; ++j)
            if (!(j & m)) ry1(x[j], x[j | m], cc, s, ns);
    }
    __half2* pl = (c ? oim : ore) + (long)p * DIM + u;
#pragma unroll
    for (int j = 0; j < 32; ++j)
        *(unsigned*)(pl + ((long)j << CHUNK_BITS)) = pk2hu(x[j]);
}

// one 4-bit stage inside pass_low
template <int LAST>
__device__ __forceinline__ void stage4(u64* sre, u64* sim, const u64 (*sgc)[6],
                                       int base, int sh, int gtop) {
    u64 re[16], im[16];
#pragma unroll
    for (int j = 0; j < 16; ++j) {
        int a = SW(base | (j << sh));
        re[j] = sre[a]; im[j] = sim[a];
    }
#pragma unroll
    for (int p = 0; p < 4; ++p) {
        const u64* g = sgc[gtop - p];
        u64 c = g[0], s = g[1], ns = g[2];
        u64 cz = g[3], sz = g[4], nsz = g[5];
        int m = 1 << p;
#pragma unroll
        for (int j = 0; j < 16; ++j)
            if (!(j & m)) {
                if (LAST) gate_ry(re[j], im[j], re[j | m], im[j | m], c, s, ns);
                else gate_ryrz(re[j], im[j], re[j | m], im[j | m], c, s, ns, cz, sz, nsz);
            }
    }
#pragma unroll
    for (int j = 0; j < 16; ++j) {
        int a = SW(base | (j << sh));
        sre[a] = re[j]; sim[a] = im[j];
    }
}

// ---------------------------------------------------------------------------
// pass_low: wires 5..17 (bits 12..0); packed fp32 SoA smem (128KB, 1 CTA/SM).
// Fill applies folded high-wire RZ phase; wire 5 fused with Gray scatter.
// LAST: RY-only + expectation values.
// ---------------------------------------------------------------------------
template <int LAST>
__global__ void __launch_bounds__(PL_THREADS, 1)
k_pass_low(const __half2* __restrict__ ire, const __half2* __restrict__ iim,
           __half2* __restrict__ ore, __half2* __restrict__ oim,
           const float* __restrict__ params, float* __restrict__ partial,
           int layer) {
    extern __shared__ u64 smem[];
    u64* sre = smem;                 // 8192 u64 = 64KB
    u64* simm = smem + CHUNK;        // 64KB
    __shared__ u64 sgc[13][6];
    int tid = threadIdx.x;

    if (tid < 13) {
        int w = 5 + tid;
        float ty = params[(layer * 2) * NUM_WIRES + w] * 0.5f;
        float tz = params[(layer * 2 + 1) * NUM_WIRES + w] * 0.5f;
        float cy = cosf(ty), sy = sinf(ty), cz = cosf(tz), sz = sinf(tz);
        sgc[tid][0] = pk2(cy); sgc[tid][1] = pk2(sy); sgc[tid][2] = pk2(-sy);
        sgc[tid][3] = pk2(cz); sgc[tid][4] = pk2(sz); sgc[tid][5] = pk2(-sz);
    }

    int b = blockIdx.x >> 5;
    int H = blockIdx.x & 31;
    long base = (long)b * DIM + ((long)H << CHUNK_BITS);

    // folded high-wire RZ phase (chunk-constant); dropped in last layer
    float pr = 1.0f, pi = 0.0f;
    if (!LAST) {
#pragma unroll
        for (int w = 0; w < 5; ++w) {
            float tz = params[(layer * 2 + 1) * NUM_WIRES + w] * 0.5f;
            float cz = cosf(tz), sz = sinf(tz);
            float zi = ((H >> (4 - w)) & 1) ? sz : -sz;
            float npr = pr * cz - pi * zi;
            float npi = pr * zi + pi * cz;
            pr = npr; pi = npi;
        }
    }
    u64 pr2 = pk2(pr), pi2 = pk2(pi), npi2 = pk2(-pi);

    // fill (+phase)
    {
        const uint4* irr = (const uint4*)(ire + base);
        const uint4* iii = (const uint4*)(iim + base);
        uint4 vr[4], vi[4];
#pragma unroll
        for (int k = 0; k < 4; ++k) { vr[k] = irr[tid + k * PL_THREADS]; vi[k] = iii[tid + k * PL_THREADS]; }
#pragma unroll
        for (int k = 0; k < 4; ++k) {
            int t = 4 * (tid + k * PL_THREADS);
            unsigned ru[4] = { vr[k].x, vr[k].y, vr[k].z, vr[k].w };
            unsigned iu[4] = { vi[k].x, vi[k].y, vi[k].z, vi[k].w };
#pragma unroll
            for (int j = 0; j < 4; ++j) {
                u64 rr = h2u_pk(ru[j]), ii = h2u_pk(iu[j]);
                if (!LAST) {
                    u64 nr = fma2(pr2, rr, mul2(npi2, ii));
                    u64 ni = fma2(pr2, ii, mul2(pi2, rr));
                    rr = nr; ii = ni;
                }
                sre[SW(t + j)] = rr; simm[SW(t + j)] = ii;
            }
        }
    }
    __syncthreads();

    stage4<LAST>(sre, simm, sgc, tid << 4, 0, 12);                          // wires 17..14
    __syncthreads();
    stage4<LAST>(sre, simm, sgc, (tid & 15) | ((tid >> 4) << 8), 4, 8);     // wires 13..10
    __syncthreads();
    stage4<LAST>(sre, simm, sgc, (tid & 255) | ((tid >> 8) << 12), 8, 4);   // wires 9..6
    __syncthreads();

    // wire 5 (bit 12) fused with CNOT-ladder permutation
    int pm = (__popc(H) & 1) ? (CHUNK - 1) : 0;
    int Hd = H ^ (H >> 1); Hd ^= Hd >> 2; Hd ^= Hd >> 4;   // invgray5
    u64 c5 = sgc[0][0], s5 = sgc[0][1], ns5 = sgc[0][2];
    u64 cz5 = sgc[0][3], sz5 = sgc[0][4], nsz5 = sgc[0][5];

    if (!LAST) {
        long obase = (long)b * DIM + ((long)Hd << CHUNK_BITS);
        __half2* dre = ore + obase;
        __half2* dim = oim + obase;
#pragma unroll
        for (int k = 0; k < 4; ++k) {
            int t = 2 * (tid + k * PL_THREADS);     // even, [0,4096)
            int uu = t + 4096;
            u64 rt = sre[SW(t)], it = simm[SW(t)];
            u64 rt1 = sre[SW(t + 1)], it1 = simm[SW(t + 1)];
            u64 ru = sre[SW(uu)], iu = simm[SW(uu)];
            u64 ru1 = sre[SW(uu + 1)], iu1 = simm[SW(uu + 1)];
            gate_ryrz(rt, it, ru, iu, c5, s5, ns5, cz5, sz5, nsz5);
            gate_ryrz(rt1, it1, ru1, iu1, c5, s5, ns5, cz5, sz5, nsz5);
            int q = invgray(t) ^ pm;
            int qu = q ^ 8191;                      // invgray(4096)=8191
            st_pair(dre, q, rt, rt1);  st_pair(dim, q, it, it1);
            st_pair(dre, qu, ru, ru1); st_pair(dim, qu, iu, iu1);
        }
    } else {
        float a0[NUM_WIRES], a1[NUM_WIRES];
#pragma unroll
        for (int w = 0; w < NUM_WIRES; ++w) { a0[w] = 0.0f; a1[w] = 0.0f; }
        int hi = Hd << CHUNK_BITS;
#pragma unroll
        for (int k = 0; k < 4; ++k) {
            int t = 2 * (tid + k * PL_THREADS);
            int uu = t + 4096;
            u64 rt = sre[SW(t)], it = simm[SW(t)];
            u64 rt1 = sre[SW(t + 1)], it1 = simm[SW(t + 1)];
            u64 ru = sre[SW(uu)], iu = simm[SW(uu)];
            u64 ru1 = sre[SW(uu + 1)], iu1 = simm[SW(uu + 1)];
            gate_ry(rt, it, ru, iu, c5, s5, ns5);
            gate_ry(rt1, it1, ru1, iu1, c5, s5, ns5);
            int q = invgray(t) ^ pm;
            int qu = q ^ 8191;
            float2 pt  = up(fma2(rt, rt, mul2(it, it)));
            float2 pt1 = up(fma2(rt1, rt1, mul2(it1, it1)));
            float2 pu  = up(fma2(ru, ru, mul2(iu, iu)));
            float2 pu1 = up(fma2(ru1, ru1, mul2(iu1, iu1)));
            {
                int d = hi | q;
                unsigned bb0 = __float_as_uint(pt.x + pt1.x);
                unsigned bb1 = __float_as_uint(pt.y + pt1.y);
#pragma unroll
                for (int w = 0; w < 17; ++w) {
                    unsigned bit = (unsigned)(d >> (17 - w)) & 1u;
                    a0[w] += __uint_as_float(bb0 ^ (bit << 31));
                    a1[w] += __uint_as_float(bb1 ^ (bit << 31));
                }
                float d0 = pt.x - pt1.x, d1 = pt.y - pt1.y;
                a0[17] += (q & 1) ? -d0 : d0;
                a1[17] += (q & 1) ? -d1 : d1;
            }
            {
                int d = hi | qu;
                unsigned bb0 = __float_as_uint(pu.x + pu1.x);
                unsigned bb1 = __float_as_uint(pu.y + pu1.y);
#pragma unroll
                for (int w = 0; w < 17; ++w) {
                    unsigned bit = (unsigned)(d >> (17 - w)) & 1u;
                    a0[w] += __uint_as_float(bb0 ^ (bit << 31));
                    a1[w] += __uint_as_float(bb1 ^ (bit << 31));
                }
                float d0 = pu.x - pu1.x, d1 = pu.y - pu1.y;
                a0[17] += (qu & 1) ? -d0 : d0;
                a1[17] += (qu & 1) ? -d1 : d1;
            }
        }
#pragma unroll
        for (int w = 0; w < NUM_WIRES; ++w)
#pragma unroll
            for (int o = 16; o; o >>= 1) {
                a0[w] += __shfl_down_sync(0xFFFFFFFFu, a0[w], o);
                a1[w] += __shfl_down_sync(0xFFFFFFFFu, a1[w], o);
            }
        __syncthreads();
        float* scratch = (float*)smem;
        int warp = tid >> 5, lane = tid & 31;
        if (lane == 0) {
#pragma unroll
            for (int w = 0; w < NUM_WIRES; ++w) {
                scratch[(warp * 2 + 0) * NUM_WIRES + w] = a0[w];
                scratch[(warp * 2 + 1) * NUM_WIRES + w] = a1[w];
            }
        }
        __syncthreads();
        if (tid < 2 * NUM_WIRES) {
            int s = tid / NUM_WIRES, w = tid % NUM_WIRES;
            float sum = 0.0f;
#pragma unroll
            for (int k = 0; k < PL_THREADS / 32; ++k)
                sum += scratch[(k * 2 + s) * NUM_WIRES + w];
            partial[(((long)(2 * b + s)) * NCHUNK + H) * NUM_WIRES + w] = sum;
        }
    }
}

__global__ void k_head(const float* __restrict__ head_w,
                       const float* __restrict__ head_b,
                       float* __restrict__ out) {
    int b = threadIdx.x;
    if (b < BATCH) {
        float s = head_b[0];
#pragma unroll
        for (int w = 0; w < NUM_WIRES; ++w) {
            float f = 0.0f;
#pragma unroll
            for (int c = 0; c < NCHUNK; ++c)
                f += g_partial[((long)b * NCHUNK + c) * NUM_WIRES + w];
            s = fmaf(f, head_w[w], s);
        }
        out[b] = s;
    }
}

extern "C" void kernel_launch(void* const* d_in, const int* in_sizes, int n_in,
                              void* d_out, int out_size) {
    const float* state_re = (const float*)d_in[0];
    const float* state_im = (const float*)d_in[1];
    const float* params   = (const float*)d_in[2];
    const float* head_w   = (const float*)d_in[3];
    const float* head_b   = (const float*)d_in[4];
    float* out = (float*)d_out;

    const int shmem = 2 * CHUNK * (int)sizeof(u64);     // 128KB
    cudaFuncSetAttribute(k_pass_low<0>, cudaFuncAttributeMaxDynamicSharedMemorySize, shmem);
    cudaFuncSetAttribute(k_pass_low<1>, cudaFuncAttributeMaxDynamicSharedMemorySize, shmem);

    static __half2 *re0 = nullptr, *im0 = nullptr, *re1 = nullptr, *im1 = nullptr;
    static float* ptp = nullptr;
    if (!re0) {
        cudaGetSymbolAddress((void**)&re0, g_re0);
        cudaGetSymbolAddress((void**)&im0, g_im0);
        cudaGetSymbolAddress((void**)&re1, g_re1);
        cudaGetSymbolAddress((void**)&im1, g_im1);
        cudaGetSymbolAddress((void**)&ptp, g_partial);
    }

    const int ph_blocks = (GP * 2 * CHUNK) / PH_THREADS;   // 1024
    const int pl_blocks = GP * NCHUNK;                     // 512

    for (int grp = 0; grp < NPAIR / GP; ++grp) {
        long poff = (long)grp * GP * DIM;       // pair-plane offset
        long soff = (long)grp * GP * 2 * DIM;   // fp32 input offset
        __half2 *r0 = re0 + poff, *i0 = im0 + poff;
        __half2 *r1 = re1 + poff, *i1 = im1 + poff;
        float* part = ptp + (long)grp * GP * 2 * NCHUNK * NUM_WIRES;

        // layer 0
        k_first<<<ph_blocks, PH_THREADS>>>(state_re + soff, state_im + soff, r0, i0, params);
        k_pass_low<0><<<pl_blocks, PL_THREADS, shmem>>>(r0, i0, r1, i1, params, part, 0);
        // layer 1
        k_pass_high<<<ph_blocks, PH_THREADS>>>(r1, i1, params, 1);
        k_pass_low<0><<<pl_blocks, PL_THREADS, shmem>>>(r1, i1, r0, i0, params, part, 1);
        // layer 2
        k_pass_high<<<ph_blocks, PH_THREADS>>>(r0, i0, params, 2);
        k_pass_low<1><<<pl_blocks, PL_THREADS, shmem>>>(r0, i0, r1, i1, params, part, 2);
    }

    k_head<<<1, 64>>>(head_w, head_b, out);
}

// round 9
// speedup vs baseline: 1.1111x; 1.0367x over previous
#include <cuda_runtime.h>
#include <cuda_fp16.h>
#include <math.h>

#define NUM_WIRES 18
#define BATCH     64
#define NPAIR     32               // two batch states packed per f32x2 lane-pair
#define DIM       262144           // 2^18
#define CHUNK_BITS 13
#define CHUNK     8192
#define NCHUNK    32
#define PL_THREADS 512
#define PH_THREADS 256

typedef unsigned long long u64;

// SoA component planes; each half2 = (state_s0, state_s1)
__device__ __half2 g_re0[NPAIR * DIM];
__device__ __half2 g_im0[NPAIR * DIM];
__device__ __half2 g_re1[NPAIR * DIM];
__device__ __half2 g_im1[NPAIR * DIM];
__device__ float g_partial[BATCH * NCHUNK * NUM_WIRES];

// ---- packed f32x2 primitives ----
__device__ __forceinline__ u64 pk(float lo, float hi) {
    u64 r; asm("mov.b64 %0,{%1,%2};" : "=l"(r) : "f"(lo), "f"(hi)); return r;
}
__device__ __forceinline__ u64 pk2(float x) { return pk(x, x); }
__device__ __forceinline__ float2 up(u64 v) {
    float2 f; asm("mov.b64 {%0,%1},%2;" : "=f"(f.x), "=f"(f.y) : "l"(v)); return f;
}
__device__ __forceinline__ u64 fma2(u64 a, u64 b, u64 c) {
    u64 d; asm("fma.rn.f32x2 %0,%1,%2,%3;" : "=l"(d) : "l"(a), "l"(b), "l"(c)); return d;
}
__device__ __forceinline__ u64 mul2(u64 a, u64 b) {
    u64 d; asm("mul.rn.f32x2 %0,%1,%2;" : "=l"(d) : "l"(a), "l"(b)); return d;
}
// half2 bits -> packed f32x2
__device__ __forceinline__ u64 h2u_pk(unsigned v) {
    __half2 h; *(unsigned*)&h = v; float2 f = __half22float2(h); return pk(f.x, f.y);
}
// packed f32x2 -> half2 bits
__device__ __forceinline__ unsigned pk2hu(u64 v) {
    float2 f = up(v); __half2 h = __floats2half2_rn(f.x, f.y); return *(unsigned*)&h;
}

// fold-XOR swizzle on 4B-word index: bank bit i = e_i ^ e_{i+5} ^ e_{i+10}
__device__ __forceinline__ int SWX(int e) { return e ^ ((e >> 5) & 31) ^ ((e >> 10) & 31); }
__device__ __forceinline__ int invgray(int t) {
    t ^= t >> 1; t ^= t >> 2; t ^= t >> 4; t ^= t >> 8; return t;
}

// fused RY then RZ on packed complex pair (a = bit0 branch)
__device__ __forceinline__ void gate_ryrz(u64& ar, u64& ai, u64& br, u64& bi,
                                          u64 c, u64 s, u64 ns, u64 cz, u64 sz, u64 nsz) {
    u64 nar = fma2(c, ar, mul2(ns, br));
    u64 nai = fma2(c, ai, mul2(ns, bi));
    u64 nbr = fma2(s, ar, mul2(c, br));
    u64 nbi = fma2(s, ai, mul2(c, bi));
    ar = fma2(cz, nar, mul2(sz, nai));
    ai = fma2(cz, nai, mul2(nsz, nar));
    br = fma2(cz, nbr, mul2(nsz, nbi));
    bi = fma2(cz, nbi, mul2(sz, nbr));
}
__device__ __forceinline__ void gate_ry(u64& ar, u64& ai, u64& br, u64& bi,
                                        u64 c, u64 s, u64 ns) {
    u64 nar = fma2(c, ar, mul2(ns, br));
    u64 nai = fma2(c, ai, mul2(ns, bi));
    br = fma2(s, ar, mul2(c, br));
    bi = fma2(s, ai, mul2(c, bi));
    ar = nar; ai = nai;
}
__device__ __forceinline__ void ry1(u64& a, u64& b, u64 c, u64 s, u64 ns) {
    u64 na = fma2(c, a, mul2(ns, b));
    b = fma2(s, a, mul2(c, b));
    a = na;
}
__device__ __forceinline__ void st_pair(__half2* pl, int q, u64 A, u64 B) {
    unsigned va = pk2hu(A), vb = pk2hu(B);
    uint2 o; o.x = (q & 1) ? vb : va; o.y = (q & 1) ? va : vb;
    *(uint2*)(pl + (q & ~1)) = o;
}

// ---------------------------------------------------------------------------
// pass_high: RY-only, wires 0..4 (bits 17..13), per component plane, in place.
// ---------------------------------------------------------------------------
__global__ void __launch_bounds__(PH_THREADS, 2)
k_pass_high(__half2* __restrict__ bre, __half2* __restrict__ bim,
            const float* __restrict__ params, int layer) {
    int gid = blockIdx.x * PH_THREADS + threadIdx.x;
    int u = gid & (CHUNK - 1);
    int r = gid >> CHUNK_BITS;          // 0..2*NPAIR-1
    __half2* pl = ((r & 1) ? bim : bre) + (long)(r >> 1) * DIM + u;

    u64 x[32];
#pragma unroll
    for (int h = 0; h < 2; ++h) {
        unsigned hb[16];
#pragma unroll
        for (int j = 0; j < 16; ++j)
            hb[j] = *(const unsigned*)(pl + ((long)(h * 16 + j) << CHUNK_BITS));
#pragma unroll
        for (int j = 0; j < 16; ++j) x[h * 16 + j] = h2u_pk(hb[j]);
    }
#pragma unroll
    for (int w = 0; w < 5; ++w) {
        float ty = params[(layer * 2) * NUM_WIRES + w] * 0.5f;
        float cy = cosf(ty), sy = sinf(ty);
        u64 c = pk2(cy), s = pk2(sy), ns = pk2(-sy);
        int m = 16 >> w;
#pragma unroll
        for (int j = 0; j < 32; ++j)
            if (!(j & m)) ry1(x[j], x[j | m], c, s, ns);
    }
#pragma unroll
    for (int j = 0; j < 32; ++j)
        *(unsigned*)(pl + ((long)j << CHUNK_BITS)) = pk2hu(x[j]);
}

// layer-0 variant: fp32 inputs (rows 2p, 2p+1) -> packed half2 planes
__global__ void __launch_bounds__(PH_THREADS, 2)
k_first(const float* __restrict__ sre, const float* __restrict__ sim,
        __half2* __restrict__ ore, __half2* __restrict__ oim,
        const float* __restrict__ params) {
    int gid = blockIdx.x * PH_THREADS + threadIdx.x;
    int u = gid & (CHUNK - 1);
    int r = gid >> CHUNK_BITS;
    int c = r & 1, p = r >> 1;
    const float* src = c ? sim : sre;
    const float* r0 = src + (long)(2 * p) * DIM + u;
    const float* r1 = src + (long)(2 * p + 1) * DIM + u;

    u64 x[32];
#pragma unroll
    for (int j = 0; j < 32; ++j)
        x[j] = pk(r0[(long)j << CHUNK_BITS], r1[(long)j << CHUNK_BITS]);
#pragma unroll
    for (int w = 0; w < 5; ++w) {
        float ty = params[w] * 0.5f;
        float cy = cosf(ty), sy = sinf(ty);
        u64 cc = pk2(cy), s = pk2(sy), ns = pk2(-sy);
        int m = 16 >> w;
#pragma unroll
        for (int j = 0; j < 32; ++j)
            if (!(j & m)) ry1(x[j], x[j | m], cc, s, ns);
    }
    __half2* pl = (c ? oim : ore) + (long)p * DIM + u;
#pragma unroll
    for (int j = 0; j < 32; ++j)
        *(unsigned*)(pl + ((long)j << CHUNK_BITS)) = pk2hu(x[j]);
}

// one 3-bit stage: 8 complex values per group, j at bit offset sh
template <int LAST>
__device__ __forceinline__ void stage3(unsigned* s_re, unsigned* s_im,
                                       const u64 (*sgc)[6], int base, int sh, int wtop) {
    u64 re[8], im[8];
#pragma unroll
    for (int j = 0; j < 8; ++j) {
        int a = SWX(base | (j << sh));
        re[j] = h2u_pk(s_re[a]); im[j] = h2u_pk(s_im[a]);
    }
#pragma unroll
    for (int p = 0; p < 3; ++p) {
        const u64* g = sgc[wtop - p];
        u64 c = g[0], s = g[1], ns = g[2];
        u64 cz = g[3], sz = g[4], nsz = g[5];
        int m = 1 << p;
#pragma unroll
        for (int j = 0; j < 8; ++j)
            if (!(j & m)) {
                if (LAST) gate_ry(re[j], im[j], re[j | m], im[j | m], c, s, ns);
                else gate_ryrz(re[j], im[j], re[j | m], im[j | m], c, s, ns, cz, sz, nsz);
            }
    }
#pragma unroll
    for (int j = 0; j < 8; ++j) {
        int a = SWX(base | (j << sh));
        s_re[a] = pk2hu(re[j]); s_im[a] = pk2hu(im[j]);
    }
}

// ---------------------------------------------------------------------------
// pass_low: wires 5..17 (bits 12..0); fp16 smem (64KB -> 2 CTAs/SM).
// Fill applies folded high-wire RZ phase; wire 5 fused with Gray scatter.
// LAST: RY-only + expectation values.
// ---------------------------------------------------------------------------
template <int LAST>
__global__ void __launch_bounds__(PL_THREADS, 2)
k_pass_low(const __half2* __restrict__ ire, const __half2* __restrict__ iim,
           __half2* __restrict__ ore, __half2* __restrict__ oim,
           const float* __restrict__ params, float* __restrict__ partial,
           int layer) {
    extern __shared__ unsigned smem_u[];
    unsigned* s_re = smem_u;             // 8192 x 4B = 32KB
    unsigned* s_im = smem_u + CHUNK;     // 32KB
    __shared__ u64 sgc[13][6];
    int tid = threadIdx.x;

    if (tid < 13) {
        int w = 5 + tid;
        float ty = params[(layer * 2) * NUM_WIRES + w] * 0.5f;
        float tz = params[(layer * 2 + 1) * NUM_WIRES + w] * 0.5f;
        float cy = cosf(ty), sy = sinf(ty), cz = cosf(tz), sz = sinf(tz);
        sgc[tid][0] = pk2(cy); sgc[tid][1] = pk2(sy); sgc[tid][2] = pk2(-sy);
        sgc[tid][3] = pk2(cz); sgc[tid][4] = pk2(sz); sgc[tid][5] = pk2(-sz);
    }

    int b = blockIdx.x >> 5;
    int H = blockIdx.x & 31;
    long base = (long)b * DIM + ((long)H << CHUNK_BITS);

    // folded high-wire RZ phase (chunk-constant); dropped in last layer
    float pr = 1.0f, pi = 0.0f;
    if (!LAST) {
#pragma unroll
        for (int w = 0; w < 5; ++w) {
            float tz = params[(layer * 2 + 1) * NUM_WIRES + w] * 0.5f;
            float cz = cosf(tz), sz = sinf(tz);
            float zi = ((H >> (4 - w)) & 1) ? sz : -sz;
            float npr = pr * cz - pi * zi;
            float npi = pr * zi + pi * cz;
            pr = npr; pi = npi;
        }
    }
    u64 pr2 = pk2(pr), pi2 = pk2(pi), npi2 = pk2(-pi);

    // fill (+phase). 4 x 16B loads per thread per plane.
    {
        const uint4* irr = (const uint4*)(ire + base);
        const uint4* iii = (const uint4*)(iim + base);
        uint4 vr[4], vi[4];
#pragma unroll
        for (int k = 0; k < 4; ++k) { vr[k] = irr[tid + k * PL_THREADS]; vi[k] = iii[tid + k * PL_THREADS]; }
#pragma unroll
        for (int k = 0; k < 4; ++k) {
            int t = 4 * (tid + k * PL_THREADS);
            unsigned ru[4] = { vr[k].x, vr[k].y, vr[k].z, vr[k].w };
            unsigned iu[4] = { vi[k].x, vi[k].y, vi[k].z, vi[k].w };
#pragma unroll
            for (int j = 0; j < 4; ++j) {
                if (LAST) {
                    s_re[SWX(t + j)] = ru[j]; s_im[SWX(t + j)] = iu[j];
                } else {
                    u64 rr = h2u_pk(ru[j]), ii = h2u_pk(iu[j]);
                    u64 nr = fma2(pr2, rr, mul2(npi2, ii));
                    u64 ni = fma2(pr2, ii, mul2(pi2, rr));
                    s_re[SWX(t + j)] = pk2hu(nr); s_im[SWX(t + j)] = pk2hu(ni);
                }
            }
        }
    }
    __syncthreads();

    // stage A: bits 0..2 (wires 17,16,15). 1024 groups, 2/thread.
#pragma unroll
    for (int i = 0; i < 2; ++i)
        stage3<LAST>(s_re, s_im, sgc, (tid + i * PL_THREADS) << 3, 0, 12);
    __syncthreads();

    // stage B: bits 3..5 (wires 14,13,12). custom lane->group map (bank-safe).
    {
        int l = tid & 31, w = tid >> 5;
#pragma unroll
        for (int i = 0; i < 2; ++i) {
            int g = (l & 7) | ((w & 3) << 3) | (((l >> 3) & 3) << 5)
                  | (((w >> 2) & 3) << 7) | (i << 9);
            int bs = (g & 7) | ((g >> 3) << 6);
            stage3<LAST>(s_re, s_im, sgc, bs, 3, 9);
        }
    }
    __syncthreads();

    // stage C: bits 6..8 (wires 11,10,9).
#pragma unroll
    for (int i = 0; i < 2; ++i) {
        int g = tid + i * PL_THREADS;
        stage3<LAST>(s_re, s_im, sgc, (g & 63) | ((g >> 6) << 9), 6, 6);
    }
    __syncthreads();

    // stage D: bits 9..11 (wires 8,7,6).
#pragma unroll
    for (int i = 0; i < 2; ++i) {
        int g = tid + i * PL_THREADS;
        stage3<LAST>(s_re, s_im, sgc, (g & 511) | ((g >> 9) << 12), 9, 3);
    }
    __syncthreads();

    // wire 5 (bit 12) fused with CNOT-ladder permutation
    int pm = (__popc(H) & 1) ? (CHUNK - 1) : 0;
    int Hd = H ^ (H >> 1); Hd ^= Hd >> 2; Hd ^= Hd >> 4;   // invgray5
    u64 c5 = sgc[0][0], s5 = sgc[0][1], ns5 = sgc[0][2];
    u64 cz5 = sgc[0][3], sz5 = sgc[0][4], nsz5 = sgc[0][5];

    if (!LAST) {
        long obase = (long)b * DIM + ((long)Hd << CHUNK_BITS);
        __half2* dre = ore + obase;
        __half2* dim = oim + obase;
#pragma unroll
        for (int k = 0; k < 4; ++k) {
            int t = 2 * (tid + k * PL_THREADS);     // even, [0,4096)
            int uu = t + 4096;
            u64 rt = h2u_pk(s_re[SWX(t)]), it = h2u_pk(s_im[SWX(t)]);
            u64 rt1 = h2u_pk(s_re[SWX(t + 1)]), it1 = h2u_pk(s_im[SWX(t + 1)]);
            u64 ru = h2u_pk(s_re[SWX(uu)]), iu = h2u_pk(s_im[SWX(uu)]);
            u64 ru1 = h2u_pk(s_re[SWX(uu + 1)]), iu1 = h2u_pk(s_im[SWX(uu + 1)]);
            gate_ryrz(rt, it, ru, iu, c5, s5, ns5, cz5, sz5, nsz5);
            gate_ryrz(rt1, it1, ru1, iu1, c5, s5, ns5, cz5, sz5, nsz5);
            int q = invgray(t) ^ pm;
            int qu = q ^ 8191;                      // invgray(4096)=8191
            st_pair(dre, q, rt, rt1);  st_pair(dim, q, it, it1);
            st_pair(dre, qu, ru, ru1); st_pair(dim, qu, iu, iu1);
        }
    } else {
        float a0[NUM_WIRES], a1[NUM_WIRES];
#pragma unroll
        for (int w = 0; w < NUM_WIRES; ++w) { a0[w] = 0.0f; a1[w] = 0.0f; }
        int hi = Hd << CHUNK_BITS;
#pragma unroll
        for (int k = 0; k < 4; ++k) {
            int t = 2 * (tid + k * PL_THREADS);
            int uu = t + 4096;
            u64 rt = h2u_pk(s_re[SWX(t)]), it = h2u_pk(s_im[SWX(t)]);
            u64 rt1 = h2u_pk(s_re[SWX(t + 1)]), it1 = h2u_pk(s_im[SWX(t + 1)]);
            u64 ru = h2u_pk(s_re[SWX(uu)]), iu = h2u_pk(s_im[SWX(uu)]);
            u64 ru1 = h2u_pk(s_re[SWX(uu + 1)]), iu1 = h2u_pk(s_im[SWX(uu + 1)]);
            gate_ry(rt, it, ru, iu, c5, s5, ns5);
            gate_ry(rt1, it1, ru1, iu1, c5, s5, ns5);
            int q = invgray(t) ^ pm;
            int qu = q ^ 8191;
            float2 pt  = up(fma2(rt, rt, mul2(it, it)));
            float2 pt1 = up(fma2(rt1, rt1, mul2(it1, it1)));
            float2 pu  = up(fma2(ru, ru, mul2(iu, iu)));
            float2 pu1 = up(fma2(ru1, ru1, mul2(iu1, iu1)));
            {
                int d = hi | q;
                unsigned bb0 = __float_as_uint(pt.x + pt1.x);
                unsigned bb1 = __float_as_uint(pt.y + pt1.y);
#pragma unroll
                for (int w = 0; w < 17; ++w) {
                    unsigned bit = (unsigned)(d >> (17 - w)) & 1u;
                    a0[w] += __uint_as_float(bb0 ^ (bit << 31));
                    a1[w] += __uint_as_float(bb1 ^ (bit << 31));
                }
                float d0 = pt.x - pt1.x, d1 = pt.y - pt1.y;
                a0[17] += (q & 1) ? -d0 : d0;
                a1[17] += (q & 1) ? -d1 : d1;
            }
            {
                int d = hi | qu;
                unsigned bb0 = __float_as_uint(pu.x + pu1.x);
                unsigned bb1 = __float_as_uint(pu.y + pu1.y);
#pragma unroll
                for (int w = 0; w < 17; ++w) {
                    unsigned bit = (unsigned)(d >> (17 - w)) & 1u;
                    a0[w] += __uint_as_float(bb0 ^ (bit << 31));
                    a1[w] += __uint_as_float(bb1 ^ (bit << 31));
                }
                float d0 = pu.x - pu1.x, d1 = pu.y - pu1.y;
                a0[17] += (qu & 1) ? -d0 : d0;
                a1[17] += (qu & 1) ? -d1 : d1;
            }
        }
#pragma unroll
        for (int w = 0; w < NUM_WIRES; ++w)
#pragma unroll
            for (int o = 16; o; o >>= 1) {
                a0[w] += __shfl_down_sync(0xFFFFFFFFu, a0[w], o);
                a1[w] += __shfl_down_sync(0xFFFFFFFFu, a1[w], o);
            }
        __syncthreads();
        float* scratch = (float*)smem_u;
        int warp = tid >> 5, lane = tid & 31;
        if (lane == 0) {
#pragma unroll
            for (int w = 0; w < NUM_WIRES; ++w) {
                scratch[(warp * 2 + 0) * NUM_WIRES + w] = a0[w];
                scratch[(warp * 2 + 1) * NUM_WIRES + w] = a1[w];
            }
        }
        __syncthreads();
        if (tid < 2 * NUM_WIRES) {
            int s = tid / NUM_WIRES, w = tid % NUM_WIRES;
            float sum = 0.0f;
#pragma unroll
            for (int k = 0; k < PL_THREADS / 32; ++k)
                sum += scratch[(k * 2 + s) * NUM_WIRES + w];
            partial[(((long)(2 * b + s)) * NCHUNK + H) * NUM_WIRES + w] = sum;
        }
    }
}

__global__ void k_head(const float* __restrict__ head_w,
                       const float* __restrict__ head_b,
                       float* __restrict__ out) {
    int b = threadIdx.x;
    if (b < BATCH) {
        float s = head_b[0];
#pragma unroll
        for (int w = 0; w < NUM_WIRES; ++w) {
            float f = 0.0f;
#pragma unroll
            for (int c = 0; c < NCHUNK; ++c)
                f += g_partial[((long)b * NCHUNK + c) * NUM_WIRES + w];
            s = fmaf(f, head_w[w], s);
        }
        out[b] = s;
    }
}

extern "C" void kernel_launch(void* const* d_in, const int* in_sizes, int n_in,
                              void* d_out, int out_size) {
    const float* state_re = (const float*)d_in[0];
    const float* state_im = (const float*)d_in[1];
    const float* params   = (const float*)d_in[2];
    const float* head_w   = (const float*)d_in[3];
    const float* head_b   = (const float*)d_in[4];
    float* out = (float*)d_out;

    const int shmem = 2 * CHUNK * (int)sizeof(unsigned);   // 64KB
    cudaFuncSetAttribute(k_pass_low<0>, cudaFuncAttributeMaxDynamicSharedMemorySize, shmem);
    cudaFuncSetAttribute(k_pass_low<1>, cudaFuncAttributeMaxDynamicSharedMemorySize, shmem);

    static __half2 *re0 = nullptr, *im0 = nullptr, *re1 = nullptr, *im1 = nullptr;
    static float* ptp = nullptr;
    if (!re0) {
        cudaGetSymbolAddress((void**)&re0, g_re0);
        cudaGetSymbolAddress((void**)&im0, g_im0);
        cudaGetSymbolAddress((void**)&re1, g_re1);
        cudaGetSymbolAddress((void**)&im1, g_im1);
        cudaGetSymbolAddress((void**)&ptp, g_partial);
    }

    const int ph_blocks = (NPAIR * 2 * CHUNK) / PH_THREADS;  // 2048
    const int pl_blocks = NPAIR * NCHUNK;                    // 1024

    // layer 0
    k_first<<<ph_blocks, PH_THREADS>>>(state_re, state_im, re0, im0, params);
    k_pass_low<0><<<pl_blocks, PL_THREADS, shmem>>>(re0, im0, re1, im1, params, ptp, 0);
    // layer 1
    k_pass_high<<<ph_blocks, PH_THREADS>>>(re1, im1, params, 1);
    k_pass_low<0><<<pl_blocks, PL_THREADS, shmem>>>(re1, im1, re0, im0, params, ptp, 1);
    // layer 2
    k_pass_high<<<ph_blocks, PH_THREADS>>>(re0, im0, params, 2);
    k_pass_low<1><<<pl_blocks, PL_THREADS, shmem>>>(re0, im0, re1, im1, params, ptp, 2);

    k_head<<<1, 64>>>(head_w, head_b, out);
}

// round 10
// speedup vs baseline: 1.3313x; 1.1981x over previous
#include <cuda_runtime.h>
#include <cuda_fp16.h>
#include <math.h>

#define NUM_WIRES 18
#define BATCH     64
#define NPAIR     32
#define GP        16               // pairs per L2-resident group (2 groups)
#define DIM       262144           // 2^18
#define CHUNK_BITS 13
#define CHUNK     8192
#define NCHUNK    32
#define PL_THREADS 512
#define PH_THREADS 256

typedef unsigned long long u64;

// SoA component planes; each half2 = (state_s0, state_s1)
__device__ __half2 g_re0[NPAIR * DIM];
__device__ __half2 g_im0[NPAIR * DIM];
__device__ __half2 g_re1[NPAIR * DIM];
__device__ __half2 g_im1[NPAIR * DIM];
__device__ float g_partial[BATCH * NCHUNK * NUM_WIRES];

// ---- packed f32x2 primitives ----
__device__ __forceinline__ u64 pk(float lo, float hi) {
    u64 r; asm("mov.b64 %0,{%1,%2};" : "=l"(r) : "f"(lo), "f"(hi)); return r;
}
__device__ __forceinline__ u64 pk2(float x) { return pk(x, x); }
__device__ __forceinline__ float2 up(u64 v) {
    float2 f; asm("mov.b64 {%0,%1},%2;" : "=f"(f.x), "=f"(f.y) : "l"(v)); return f;
}
__device__ __forceinline__ u64 fma2(u64 a, u64 b, u64 c) {
    u64 d; asm("fma.rn.f32x2 %0,%1,%2,%3;" : "=l"(d) : "l"(a), "l"(b), "l"(c)); return d;
}
__device__ __forceinline__ u64 mul2(u64 a, u64 b) {
    u64 d; asm("mul.rn.f32x2 %0,%1,%2;" : "=l"(d) : "l"(a), "l"(b)); return d;
}
__device__ __forceinline__ u64 h2u_pk(unsigned v) {
    __half2 h; *(unsigned*)&h = v; float2 f = __half22float2(h); return pk(f.x, f.y);
}
__device__ __forceinline__ unsigned pk2hu(u64 v) {
    float2 f = up(v); __half2 h = __floats2half2_rn(f.x, f.y); return *(unsigned*)&h;
}

// fold-XOR swizzle on 4B-word index: bank bit i = e_i ^ e_{i+5} ^ e_{i+10}
__device__ __forceinline__ int SWX(int e) { return e ^ ((e >> 5) & 31) ^ ((e >> 10) & 31); }
__device__ __forceinline__ int invgray(int t) {
    t ^= t >> 1; t ^= t >> 2; t ^= t >> 4; t ^= t >> 8; return t;
}

// real RY butterfly on packed pair (a = bit0 branch)
__device__ __forceinline__ void ry1(u64& a, u64& b, u64 c, u64 s, u64 ns) {
    u64 na = fma2(c, a, mul2(ns, b));
    b = fma2(s, a, mul2(c, b));
    a = na;
}
// complex phase multiply on packed amplitude
__device__ __forceinline__ void capply(u64& r, u64& i, float2 p) {
    u64 pr = pk2(p.x), pi = pk2(p.y), npi = pk2(-p.y);
    u64 nr = fma2(pr, r, mul2(npi, i));
    i = fma2(pr, i, mul2(pi, r));
    r = nr;
}
__device__ __forceinline__ float2 cmulf(float2 a, float2 b) {
    return make_float2(a.x * b.x - a.y * b.y, a.x * b.y + a.y * b.x);
}
__device__ __forceinline__ void st_pair(__half2* pl, int q, u64 A, u64 B) {
    unsigned va = pk2hu(A), vb = pk2hu(B);
    uint2 o; o.x = (q & 1) ? vb : va; o.y = (q & 1) ? va : vb;
    *(uint2*)(pl + (q & ~1)) = o;
}

// ---------------------------------------------------------------------------
// pass_high: RY-only, wires 0..4 (bits 17..13), per component plane, in place.
// ---------------------------------------------------------------------------
__global__ void __launch_bounds__(PH_THREADS, 2)
k_pass_high(__half2* __restrict__ bre, __half2* __restrict__ bim,
            const float* __restrict__ params, int layer) {
    int gid = blockIdx.x * PH_THREADS + threadIdx.x;
    int u = gid & (CHUNK - 1);
    int r = gid >> CHUNK_BITS;
    __half2* pl = ((r & 1) ? bim : bre) + (long)(r >> 1) * DIM + u;

    u64 x[32];
#pragma unroll
    for (int h = 0; h < 2; ++h) {
        unsigned hb[16];
#pragma unroll
        for (int j = 0; j < 16; ++j)
            hb[j] = *(const unsigned*)(pl + ((long)(h * 16 + j) << CHUNK_BITS));
#pragma unroll
        for (int j = 0; j < 16; ++j) x[h * 16 + j] = h2u_pk(hb[j]);
    }
#pragma unroll
    for (int w = 0; w < 5; ++w) {
        float ty = params[(layer * 2) * NUM_WIRES + w] * 0.5f;
        float cy = cosf(ty), sy = sinf(ty);
        u64 c = pk2(cy), s = pk2(sy), ns = pk2(-sy);
        int m = 16 >> w;
#pragma unroll
        for (int j = 0; j < 32; ++j)
            if (!(j & m)) ry1(x[j], x[j | m], c, s, ns);
    }
#pragma unroll
    for (int j = 0; j < 32; ++j)
        *(unsigned*)(pl + ((long)j << CHUNK_BITS)) = pk2hu(x[j]);
}

// layer-0 variant: fp32 inputs (rows 2p, 2p+1) -> packed half2 planes
__global__ void __launch_bounds__(PH_THREADS, 2)
k_first(const float* __restrict__ sre, const float* __restrict__ sim,
        __half2* __restrict__ ore, __half2* __restrict__ oim,
        const float* __restrict__ params) {
    int gid = blockIdx.x * PH_THREADS + threadIdx.x;
    int u = gid & (CHUNK - 1);
    int r = gid >> CHUNK_BITS;
    int c = r & 1, p = r >> 1;
    const float* src = c ? sim : sre;
    const float* r0 = src + (long)(2 * p) * DIM + u;
    const float* r1 = src + (long)(2 * p + 1) * DIM + u;

    u64 x[32];
#pragma unroll
    for (int j = 0; j < 32; ++j)
        x[j] = pk(r0[(long)j << CHUNK_BITS], r1[(long)j << CHUNK_BITS]);
#pragma unroll
    for (int w = 0; w < 5; ++w) {
        float ty = params[w] * 0.5f;
        float cy = cosf(ty), sy = sinf(ty);
        u64 cc = pk2(cy), s = pk2(sy), ns = pk2(-sy);
        int m = 16 >> w;
#pragma unroll
        for (int j = 0; j < 32; ++j)
            if (!(j & m)) ry1(x[j], x[j | m], cc, s, ns);
    }
    __half2* pl = (c ? oim : ore) + (long)p * DIM + u;
#pragma unroll
    for (int j = 0; j < 32; ++j)
        *(unsigned*)(pl + ((long)j << CHUNK_BITS)) = pk2hu(x[j]);
}

// 4-bit RY stage on ONE plane: 16 values per group, bit offset sh.
// wi0 = sgc index of the p=0 wire (wire idx decreases with p).
__device__ __forceinline__ void stage4p(unsigned* pl, const u64 (*sg)[3],
                                        int base, int sh, int wi0) {
    u64 x[16];
#pragma unroll
    for (int j = 0; j < 16; ++j) x[j] = h2u_pk(pl[SWX(base | (j << sh))]);
#pragma unroll
    for (int p = 0; p < 4; ++p) {
        u64 c = sg[wi0 - p][0], s = sg[wi0 - p][1], ns = sg[wi0 - p][2];
        int m = 1 << p;
#pragma unroll
        for (int j = 0; j < 16; ++j)
            if (!(j & m)) ry1(x[j], x[j | m], c, s, ns);
    }
#pragma unroll
    for (int j = 0; j < 16; ++j) pl[SWX(base | (j << sh))] = pk2hu(x[j]);
}

// ---------------------------------------------------------------------------
// pass_low: wires 5..17 (bits 12..0); fp16 smem (64KB -> 2 CTAs/SM).
// RY-only stages (per plane); all low-wire RZs collapsed into one diagonal
// phase multiply (P_lo x P_hi tables; chunk-const high-wire RZ folded into
// P_hi) applied at the scatter. Wire 5 RY fused with Gray scatter.
// LAST: no RZ anywhere; expectation values instead of state write.
// ---------------------------------------------------------------------------
template <int LAST>
__global__ void __launch_bounds__(PL_THREADS, 2)
k_pass_low(const __half2* __restrict__ ire, const __half2* __restrict__ iim,
           __half2* __restrict__ ore, __half2* __restrict__ oim,
           const float* __restrict__ params, float* __restrict__ partial,
           int layer) {
    extern __shared__ unsigned smem_u[];
    unsigned* s_re = smem_u;             // 8192 x 4B = 32KB
    unsigned* s_im = smem_u + CHUNK;     // 32KB
    __shared__ u64 sg[13][3];            // RY coefs, wires 5..17 -> [w-5]
    __shared__ float2 Plo[64];           // phase for bits 0..5 (wires 17..12)
    __shared__ float2 Phi[128];          // phase for bits 6..12 + chunk phase
    int tid = threadIdx.x;

    int b = blockIdx.x >> 5;
    int H = blockIdx.x & 31;

    if (tid < 13) {
        float ty = params[(layer * 2) * NUM_WIRES + (5 + tid)] * 0.5f;
        float cy = cosf(ty), sy = sinf(ty);
        sg[tid][0] = pk2(cy); sg[tid][1] = pk2(sy); sg[tid][2] = pk2(-sy);
    }
    if (!LAST && tid >= 32 && tid < 224) {
        int i = tid - 32;
        const float* tz = params + (layer * 2 + 1) * NUM_WIRES;
        if (i < 64) {
            float ang = 0.0f;
#pragma unroll
            for (int bb = 0; bb < 6; ++bb) {
                float h = tz[17 - bb] * 0.5f;
                ang += ((i >> bb) & 1) ? h : -h;
            }
            float sv, cv; sincosf(ang, &sv, &cv);
            Plo[i] = make_float2(cv, sv);
        } else {
            int hv = i - 64;
            float ang = 0.0f;
#pragma unroll
            for (int w = 0; w < 5; ++w) {           // chunk-const high-wire RZ
                float h = tz[w] * 0.5f;
                ang += ((H >> (4 - w)) & 1) ? h : -h;
            }
#pragma unroll
            for (int bb = 6; bb <= 12; ++bb) {
                float h = tz[17 - bb] * 0.5f;
                ang += ((hv >> (bb - 6)) & 1) ? h : -h;
            }
            float sv, cv; sincosf(ang, &sv, &cv);
            Phi[hv] = make_float2(cv, sv);
        }
    }

    long base = (long)b * DIM + ((long)H << CHUNK_BITS);

    // fill: pure convert (no phase math)
    {
        const uint4* irr = (const uint4*)(ire + base);
        const uint4* iii = (const uint4*)(iim + base);
        uint4 vr[4], vi[4];
#pragma unroll
        for (int k = 0; k < 4; ++k) { vr[k] = irr[tid + k * PL_THREADS]; vi[k] = iii[tid + k * PL_THREADS]; }
#pragma unroll
        for (int k = 0; k < 4; ++k) {
            int t = 4 * (tid + k * PL_THREADS);
            s_re[SWX(t)]     = vr[k].x; s_im[SWX(t)]     = vi[k].x;
            s_re[SWX(t + 1)] = vr[k].y; s_im[SWX(t + 1)] = vi[k].y;
            s_re[SWX(t + 2)] = vr[k].z; s_im[SWX(t + 2)] = vi[k].z;
            s_re[SWX(t + 3)] = vr[k].w; s_im[SWX(t + 3)] = vi[k].w;
        }
    }
    __syncthreads();

    // stage A: bits 0..3 (wires 17..14); 512 groups, 1/thread.
    {
        int bs = tid << 4;
        stage4p(s_re, sg, bs, 0, 12);
        stage4p(s_im, sg, bs, 0, 12);
    }
    __syncthreads();

    // stage B: bits 4..7 (wires 13..10). Bank-safe custom map:
    // e = (tid&15) | (w0<<8) | (l4<<9) | ((w>>1)<<10), w=tid>>5, l4=(tid>>4)&1
    {
        int w = tid >> 5;
        int bs = (tid & 15) | ((w & 1) << 8) | (((tid >> 4) & 1) << 9) | ((w >> 1) << 10);
        stage4p(s_re, sg, bs, 4, 8);
        stage4p(s_im, sg, bs, 4, 8);
    }
    __syncthreads();

    // stage C: bits 8..11 (wires 9..6).
    {
        int bs = (tid & 255) | ((tid >> 8) << 12);
        stage4p(s_re, sg, bs, 8, 4);
        stage4p(s_im, sg, bs, 8, 4);
    }
    __syncthreads();

    // wire 5 (bit 12) RY + diagonal RZ + CNOT-ladder permutation
    int pm = (__popc(H) & 1) ? (CHUNK - 1) : 0;
    int Hd = H ^ (H >> 1); Hd ^= Hd >> 2; Hd ^= Hd >> 4;   // invgray5
    u64 c5 = sg[0][0], s5 = sg[0][1], ns5 = sg[0][2];

    if (!LAST) {
        long obase = (long)b * DIM + ((long)Hd << CHUNK_BITS);
        __half2* dre = ore + obase;
        __half2* dim = oim + obase;
#pragma unroll
        for (int k = 0; k < 4; ++k) {
            int t = 2 * (tid + k * PL_THREADS);     // even, [0,4096)
            int uu = t + 4096;
            u64 rt = h2u_pk(s_re[SWX(t)]),       it = h2u_pk(s_im[SWX(t)]);
            u64 rt1 = h2u_pk(s_re[SWX(t + 1)]),  it1 = h2u_pk(s_im[SWX(t + 1)]);
            u64 ru = h2u_pk(s_re[SWX(uu)]),      iu = h2u_pk(s_im[SWX(uu)]);
            u64 ru1 = h2u_pk(s_re[SWX(uu + 1)]), iu1 = h2u_pk(s_im[SWX(uu + 1)]);
            ry1(rt, ru, c5, s5, ns5);   ry1(it, iu, c5, s5, ns5);
            ry1(rt1, ru1, c5, s5, ns5); ry1(it1, iu1, c5, s5, ns5);
            float2 lo0 = Plo[t & 63], lo1 = Plo[(t & 63) | 1];
            float2 hT = Phi[t >> 6], hU = Phi[(t >> 6) + 64];
            capply(rt, it, cmulf(lo0, hT));   capply(rt1, it1, cmulf(lo1, hT));
            capply(ru, iu, cmulf(lo0, hU));   capply(ru1, iu1, cmulf(lo1, hU));
            int q = invgray(t) ^ pm;
            int qu = q ^ 8191;                      // invgray(4096)=8191
            st_pair(dre, q, rt, rt1);  st_pair(dim, q, it, it1);
            st_pair(dre, qu, ru, ru1); st_pair(dim, qu, iu, iu1);
        }
    } else {
        float a0[NUM_WIRES], a1[NUM_WIRES];
#pragma unroll
        for (int w = 0; w < NUM_WIRES; ++w) { a0[w] = 0.0f; a1[w] = 0.0f; }
        int hi = Hd << CHUNK_BITS;
#pragma unroll
        for (int k = 0; k < 4; ++k) {
            int t = 2 * (tid + k * PL_THREADS);
            int uu = t + 4096;
            u64 rt = h2u_pk(s_re[SWX(t)]),       it = h2u_pk(s_im[SWX(t)]);
            u64 rt1 = h2u_pk(s_re[SWX(t + 1)]),  it1 = h2u_pk(s_im[SWX(t + 1)]);
            u64 ru = h2u_pk(s_re[SWX(uu)]),      iu = h2u_pk(s_im[SWX(uu)]);
            u64 ru1 = h2u_pk(s_re[SWX(uu + 1)]), iu1 = h2u_pk(s_im[SWX(uu + 1)]);
            ry1(rt, ru, c5, s5, ns5);   ry1(it, iu, c5, s5, ns5);
            ry1(rt1, ru1, c5, s5, ns5); ry1(it1, iu1, c5, s5, ns5);
            int q = invgray(t) ^ pm;
            int qu = q ^ 8191;
            float2 pt  = up(fma2(rt, rt, mul2(it, it)));
            float2 pt1 = up(fma2(rt1, rt1, mul2(it1, it1)));
            float2 pu  = up(fma2(ru, ru, mul2(iu, iu)));
            float2 pu1 = up(fma2(ru1, ru1, mul2(iu1, iu1)));
            {
                int d = hi | q;
                unsigned bb0 = __float_as_uint(pt.x + pt1.x);
                unsigned bb1 = __float_as_uint(pt.y + pt1.y);
#pragma unroll
                for (int w = 0; w < 17; ++w) {
                    unsigned bit = (unsigned)(d >> (17 - w)) & 1u;
                    a0[w] += __uint_as_float(bb0 ^ (bit << 31));
                    a1[w] += __uint_as_float(bb1 ^ (bit << 31));
                }
                float d0 = pt.x - pt1.x, d1 = pt.y - pt1.y;
                a0[17] += (q & 1) ? -d0 : d0;
                a1[17] += (q & 1) ? -d1 : d1;
            }
            {
                int d = hi | qu;
                unsigned bb0 = __float_as_uint(pu.x + pu1.x);
                unsigned bb1 = __float_as_uint(pu.y + pu1.y);
#pragma unroll
                for (int w = 0; w < 17; ++w) {
                    unsigned bit = (unsigned)(d >> (17 - w)) & 1u;
                    a0[w] += __uint_as_float(bb0 ^ (bit << 31));
                    a1[w] += __uint_as_float(bb1 ^ (bit << 31));
                }
                float d0 = pu.x - pu1.x, d1 = pu.y - pu1.y;
                a0[17] += (qu & 1) ? -d0 : d0;
                a1[17] += (qu & 1) ? -d1 : d1;
            }
        }
#pragma unroll
        for (int w = 0; w < NUM_WIRES; ++w)
#pragma unroll
            for (int o = 16; o; o >>= 1) {
                a0[w] += __shfl_down_sync(0xFFFFFFFFu, a0[w], o);
                a1[w] += __shfl_down_sync(0xFFFFFFFFu, a1[w], o);
            }
        __syncthreads();
        float* scratch = (float*)smem_u;
        int warp = tid >> 5, lane = tid & 31;
        if (lane == 0) {
#pragma unroll
            for (int w = 0; w < NUM_WIRES; ++w) {
                scratch[(warp * 2 + 0) * NUM_WIRES + w] = a0[w];
                scratch[(warp * 2 + 1) * NUM_WIRES + w] = a1[w];
            }
        }
        __syncthreads();
        if (tid < 2 * NUM_WIRES) {
            int s = tid / NUM_WIRES, w = tid % NUM_WIRES;
            float sum = 0.0f;
#pragma unroll
            for (int k = 0; k < PL_THREADS / 32; ++k)
                sum += scratch[(k * 2 + s) * NUM_WIRES + w];
            partial[(((long)(2 * b + s)) * NCHUNK + H) * NUM_WIRES + w] = sum;
        }
    }
}

__global__ void k_head(const float* __restrict__ head_w,
                       const float* __restrict__ head_b,
                       float* __restrict__ out) {
    int b = threadIdx.x;
    if (b < BATCH) {
        float s = head_b[0];
#pragma unroll
        for (int w = 0; w < NUM_WIRES; ++w) {
            float f = 0.0f;
#pragma unroll
            for (int c = 0; c < NCHUNK; ++c)
                f += g_partial[((long)b * NCHUNK + c) * NUM_WIRES + w];
            s = fmaf(f, head_w[w], s);
        }
        out[b] = s;
    }
}

extern "C" void kernel_launch(void* const* d_in, const int* in_sizes, int n_in,
                              void* d_out, int out_size) {
    const float* state_re = (const float*)d_in[0];
    const float* state_im = (const float*)d_in[1];
    const float* params   = (const float*)d_in[2];
    const float* head_w   = (const float*)d_in[3];
    const float* head_b   = (const float*)d_in[4];
    float* out = (float*)d_out;

    const int shmem = 2 * CHUNK * (int)sizeof(unsigned);   // 64KB
    cudaFuncSetAttribute(k_pass_low<0>, cudaFuncAttributeMaxDynamicSharedMemorySize, shmem);
    cudaFuncSetAttribute(k_pass_low<1>, cudaFuncAttributeMaxDynamicSharedMemorySize, shmem);

    static __half2 *re0 = nullptr, *im0 = nullptr, *re1 = nullptr, *im1 = nullptr;
    static float* ptp = nullptr;
    if (!re0) {
        cudaGetSymbolAddress((void**)&re0, g_re0);
        cudaGetSymbolAddress((void**)&im0, g_im0);
        cudaGetSymbolAddress((void**)&re1, g_re1);
        cudaGetSymbolAddress((void**)&im1, g_im1);
        cudaGetSymbolAddress((void**)&ptp, g_partial);
    }

    const int ph_blocks = (GP * 2 * CHUNK) / PH_THREADS;   // 1024
    const int pl_blocks = GP * NCHUNK;                     // 512

    // L2-resident groups of GP=16 pairs (working set 67MB < L2)
    for (int grp = 0; grp < NPAIR / GP; ++grp) {
        long poff = (long)grp * GP * DIM;       // pair-plane offset
        long soff = (long)grp * GP * 2 * DIM;   // fp32 input offset
        __half2 *r0 = re0 + poff, *i0 = im0 + poff;
        __half2 *r1 = re1 + poff, *i1 = im1 + poff;
        float* part = ptp + (long)grp * GP * 2 * NCHUNK * NUM_WIRES;

        // layer 0
        k_first<<<ph_blocks, PH_THREADS>>>(state_re + soff, state_im + soff, r0, i0, params);
        k_pass_low<0><<<pl_blocks, PL_THREADS, shmem>>>(r0, i0, r1, i1, params, part, 0);
        // layer 1
        k_pass_high<<<ph_blocks, PH_THREADS>>>(r1, i1, params, 1);
        k_pass_low<0><<<pl_blocks, PL_THREADS, shmem>>>(r1, i1, r0, i0, params, part, 1);
        // layer 2
        k_pass_high<<<ph_blocks, PH_THREADS>>>(r0, i0, params, 2);
        k_pass_low<1><<<pl_blocks, PL_THREADS, shmem>>>(r0, i0, r1, i1, params, part, 2);
    }

    k_head<<<1, 64>>>(head_w, head_b, out);
}

// round 11
// speedup vs baseline: 1.3941x; 1.0472x over previous
#include <cuda_runtime.h>
#include <cuda_fp16.h>
#include <math.h>

#define NUM_WIRES 18
#define BATCH     64
#define NPAIR     32
#define GP        16               // pairs per L2-resident group (2 groups)
#define DIM       262144           // 2^18
#define CHUNK_BITS 13
#define CHUNK     8192
#define NCHUNK    32
#define PL_THREADS 512
#define PH_THREADS 256

typedef unsigned long long u64;

// SoA component planes; each half2 = (state_s0, state_s1)
__device__ __half2 g_re0[NPAIR * DIM];
__device__ __half2 g_im0[NPAIR * DIM];
__device__ __half2 g_re1[NPAIR * DIM];
__device__ __half2 g_im1[NPAIR * DIM];
__device__ float g_partial[BATCH * NCHUNK * NUM_WIRES];

// ---- packed f32x2 primitives ----
__device__ __forceinline__ u64 pk(float lo, float hi) {
    u64 r; asm("mov.b64 %0,{%1,%2};" : "=l"(r) : "f"(lo), "f"(hi)); return r;
}
__device__ __forceinline__ u64 pk2(float x) { return pk(x, x); }
__device__ __forceinline__ float2 up(u64 v) {
    float2 f; asm("mov.b64 {%0,%1},%2;" : "=f"(f.x), "=f"(f.y) : "l"(v)); return f;
}
__device__ __forceinline__ u64 fma2(u64 a, u64 b, u64 c) {
    u64 d; asm("fma.rn.f32x2 %0,%1,%2,%3;" : "=l"(d) : "l"(a), "l"(b), "l"(c)); return d;
}
__device__ __forceinline__ u64 mul2(u64 a, u64 b) {
    u64 d; asm("mul.rn.f32x2 %0,%1,%2;" : "=l"(d) : "l"(a), "l"(b)); return d;
}
__device__ __forceinline__ u64 h2u_pk(unsigned v) {
    __half2 h; *(unsigned*)&h = v; float2 f = __half22float2(h); return pk(f.x, f.y);
}
__device__ __forceinline__ unsigned pk2hu(u64 v) {
    float2 f = up(v); __half2 h = __floats2half2_rn(f.x, f.y); return *(unsigned*)&h;
}

// fold-XOR swizzle on 4B-word index: bank bit i = e_i ^ e_{i+5} ^ e_{i+10}
__device__ __forceinline__ int SWX(int e) { return e ^ ((e >> 5) & 31) ^ ((e >> 10) & 31); }
__device__ __forceinline__ int invgray(int t) {
    t ^= t >> 1; t ^= t >> 2; t ^= t >> 4; t ^= t >> 8; return t;
}

// real RY butterfly on packed pair (a = bit0 branch)
__device__ __forceinline__ void ry1(u64& a, u64& b, u64 c, u64 s, u64 ns) {
    u64 na = fma2(c, a, mul2(ns, b));
    b = fma2(s, a, mul2(c, b));
    a = na;
}
// complex phase multiply on packed amplitude
__device__ __forceinline__ void capply(u64& r, u64& i, float2 p) {
    u64 pr = pk2(p.x), pi = pk2(p.y), npi = pk2(-p.y);
    u64 nr = fma2(pr, r, mul2(npi, i));
    i = fma2(pr, i, mul2(pi, r));
    r = nr;
}
__device__ __forceinline__ float2 cmulf(float2 a, float2 b) {
    return make_float2(a.x * b.x - a.y * b.y, a.x * b.y + a.y * b.x);
}
__device__ __forceinline__ void st_pair(__half2* pl, int q, u64 A, u64 B) {
    unsigned va = pk2hu(A), vb = pk2hu(B);
    uint2 o; o.x = (q & 1) ? vb : va; o.y = (q & 1) ? va : vb;
    *(uint2*)(pl + (q & ~1)) = o;
}

// ---------------------------------------------------------------------------
// pass_high: RY-only, wires 0..4 (bits 17..13), per component plane, in place.
// ---------------------------------------------------------------------------
__global__ void __launch_bounds__(PH_THREADS, 2)
k_pass_high(__half2* __restrict__ bre, __half2* __restrict__ bim,
            const float* __restrict__ params, int layer) {
    int gid = blockIdx.x * PH_THREADS + threadIdx.x;
    int u = gid & (CHUNK - 1);
    int r = gid >> CHUNK_BITS;
    __half2* pl = ((r & 1) ? bim : bre) + (long)(r >> 1) * DIM + u;

    u64 x[32];
#pragma unroll
    for (int h = 0; h < 2; ++h) {
        unsigned hb[16];
#pragma unroll
        for (int j = 0; j < 16; ++j)
            hb[j] = *(const unsigned*)(pl + ((long)(h * 16 + j) << CHUNK_BITS));
#pragma unroll
        for (int j = 0; j < 16; ++j) x[h * 16 + j] = h2u_pk(hb[j]);
    }
#pragma unroll
    for (int w = 0; w < 5; ++w) {
        float ty = params[(layer * 2) * NUM_WIRES + w] * 0.5f;
        float sy, cy; sincosf(ty, &sy, &cy);
        u64 c = pk2(cy), s = pk2(sy), ns = pk2(-sy);
        int m = 16 >> w;
#pragma unroll
        for (int j = 0; j < 32; ++j)
            if (!(j & m)) ry1(x[j], x[j | m], c, s, ns);
    }
#pragma unroll
    for (int j = 0; j < 32; ++j)
        *(unsigned*)(pl + ((long)j << CHUNK_BITS)) = pk2hu(x[j]);
}

// layer-0 variant: fp32 inputs (rows 2p, 2p+1) -> packed half2 planes
__global__ void __launch_bounds__(PH_THREADS, 2)
k_first(const float* __restrict__ sre, const float* __restrict__ sim,
        __half2* __restrict__ ore, __half2* __restrict__ oim,
        const float* __restrict__ params) {
    int gid = blockIdx.x * PH_THREADS + threadIdx.x;
    int u = gid & (CHUNK - 1);
    int r = gid >> CHUNK_BITS;
    int c = r & 1, p = r >> 1;
    const float* src = c ? sim : sre;
    const float* r0 = src + (long)(2 * p) * DIM + u;
    const float* r1 = src + (long)(2 * p + 1) * DIM + u;

    u64 x[32];
#pragma unroll
    for (int j = 0; j < 32; ++j)
        x[j] = pk(r0[(long)j << CHUNK_BITS], r1[(long)j << CHUNK_BITS]);
#pragma unroll
    for (int w = 0; w < 5; ++w) {
        float ty = params[w] * 0.5f;
        float sy, cy; sincosf(ty, &sy, &cy);
        u64 cc = pk2(cy), s = pk2(sy), ns = pk2(-sy);
        int m = 16 >> w;
#pragma unroll
        for (int j = 0; j < 32; ++j)
            if (!(j & m)) ry1(x[j], x[j | m], cc, s, ns);
    }
    __half2* pl = (c ? oim : ore) + (long)p * DIM + u;
#pragma unroll
    for (int j = 0; j < 32; ++j)
        *(unsigned*)(pl + ((long)j << CHUNK_BITS)) = pk2hu(x[j]);
}

// 4-bit RY stage on ONE plane: 16 values per group, bit offset sh.
__device__ __forceinline__ void stage4p(unsigned* pl, const u64 (*sg)[3],
                                        int base, int sh, int wi0) {
    u64 x[16];
#pragma unroll
    for (int j = 0; j < 16; ++j) x[j] = h2u_pk(pl[SWX(base | (j << sh))]);
#pragma unroll
    for (int p = 0; p < 4; ++p) {
        u64 c = sg[wi0 - p][0], s = sg[wi0 - p][1], ns = sg[wi0 - p][2];
        int m = 1 << p;
#pragma unroll
        for (int j = 0; j < 16; ++j)
            if (!(j & m)) ry1(x[j], x[j | m], c, s, ns);
    }
#pragma unroll
    for (int j = 0; j < 16; ++j) pl[SWX(base | (j << sh))] = pk2hu(x[j]);
}

// ---------------------------------------------------------------------------
// pass_low: wires 5..17 (bits 12..0); fp16 smem (64KB -> 2 CTAs/SM).
// Fill fuses the bits 0..3 stage (wires 17..14) in registers; then two
// 4-bit smem stages (bits 4..7, 8..11); wire 5 (bit 12) + diagonal RZ phase
// fused with the Gray scatter. LAST: expectation values, no RZ.
// ---------------------------------------------------------------------------
template <int LAST>
__global__ void __launch_bounds__(PL_THREADS, 2)
k_pass_low(const __half2* __restrict__ ire, const __half2* __restrict__ iim,
           __half2* __restrict__ ore, __half2* __restrict__ oim,
           const float* __restrict__ params, float* __restrict__ partial,
           int layer) {
    extern __shared__ unsigned smem_u[];
    unsigned* s_re = smem_u;             // 8192 x 4B = 32KB
    unsigned* s_im = smem_u + CHUNK;     // 32KB
    __shared__ u64 sg[13][3];            // RY coefs, wires 5..17 -> [w-5]
    __shared__ float2 Plo[64];           // phase for bits 0..5 (wires 17..12)
    __shared__ float2 Phi[128];          // phase for bits 6..12 + chunk phase
    int tid = threadIdx.x;

    int b = blockIdx.x >> 5;
    int H = blockIdx.x & 31;

    if (tid < 13) {
        float ty = params[(layer * 2) * NUM_WIRES + (5 + tid)] * 0.5f;
        float sy, cy; sincosf(ty, &sy, &cy);
        sg[tid][0] = pk2(cy); sg[tid][1] = pk2(sy); sg[tid][2] = pk2(-sy);
    }
    if (!LAST && tid >= 32 && tid < 224) {
        int i = tid - 32;
        const float* tz = params + (layer * 2 + 1) * NUM_WIRES;
        if (i < 64) {
            float ang = 0.0f;
#pragma unroll
            for (int bb = 0; bb < 6; ++bb) {
                float h = tz[17 - bb] * 0.5f;
                ang += ((i >> bb) & 1) ? h : -h;
            }
            float sv, cv; sincosf(ang, &sv, &cv);
            Plo[i] = make_float2(cv, sv);
        } else {
            int hv = i - 64;
            float ang = 0.0f;
#pragma unroll
            for (int w = 0; w < 5; ++w) {           // chunk-const high-wire RZ
                float h = tz[w] * 0.5f;
                ang += ((H >> (4 - w)) & 1) ? h : -h;
            }
#pragma unroll
            for (int bb = 6; bb <= 12; ++bb) {
                float h = tz[17 - bb] * 0.5f;
                ang += ((hv >> (bb - 6)) & 1) ? h : -h;
            }
            float sv, cv; sincosf(ang, &sv, &cv);
            Phi[hv] = make_float2(cv, sv);
        }
    }

    long base = (long)b * DIM + ((long)H << CHUNK_BITS);

    // fill + fused bits 0..3 stage (wires 17..14): thread owns 16 consecutive
    // elements (4 x uint4 per plane).
    {
        const uint4* irr = (const uint4*)(ire + base);
        const uint4* iii = (const uint4*)(iim + base);
        uint4 vr[4], vi[4];
#pragma unroll
        for (int k = 0; k < 4; ++k) { vr[k] = irr[4 * tid + k]; vi[k] = iii[4 * tid + k]; }
        // coefficients must be visible before use
        __syncthreads();
        int t0 = tid << 4;
        // re plane
        {
            u64 x[16];
#pragma unroll
            for (int k = 0; k < 4; ++k) {
                x[4 * k]     = h2u_pk(vr[k].x);
                x[4 * k + 1] = h2u_pk(vr[k].y);
                x[4 * k + 2] = h2u_pk(vr[k].z);
                x[4 * k + 3] = h2u_pk(vr[k].w);
            }
#pragma unroll
            for (int p = 0; p < 4; ++p) {
                u64 c = sg[12 - p][0], s = sg[12 - p][1], ns = sg[12 - p][2];
                int m = 1 << p;
#pragma unroll
                for (int j = 0; j < 16; ++j)
                    if (!(j & m)) ry1(x[j], x[j | m], c, s, ns);
            }
#pragma unroll
            for (int j = 0; j < 16; ++j) s_re[SWX(t0 + j)] = pk2hu(x[j]);
        }
        // im plane
        {
            u64 x[16];
#pragma unroll
            for (int k = 0; k < 4; ++k) {
                x[4 * k]     = h2u_pk(vi[k].x);
                x[4 * k + 1] = h2u_pk(vi[k].y);
                x[4 * k + 2] = h2u_pk(vi[k].z);
                x[4 * k + 3] = h2u_pk(vi[k].w);
            }
#pragma unroll
            for (int p = 0; p < 4; ++p) {
                u64 c = sg[12 - p][0], s = sg[12 - p][1], ns = sg[12 - p][2];
                int m = 1 << p;
#pragma unroll
                for (int j = 0; j < 16; ++j)
                    if (!(j & m)) ry1(x[j], x[j | m], c, s, ns);
            }
#pragma unroll
            for (int j = 0; j < 16; ++j) s_im[SWX(t0 + j)] = pk2hu(x[j]);
        }
    }
    __syncthreads();

    // stage A: bits 4..7 (wires 13..10). Bank-safe map (group bits 0-3,8-12).
    {
        int w = tid >> 5;
        int bs = (tid & 15) | ((w & 1) << 8) | (((tid >> 4) & 1) << 9) | ((w >> 1) << 10);
        stage4p(s_re, sg, bs, 4, 8);
        stage4p(s_im, sg, bs, 4, 8);
    }
    __syncthreads();

    // stage B: bits 8..11 (wires 9..6). Group bits 0-7, 12.
    {
        int bs = (tid & 255) | ((tid >> 8) << 12);
        stage4p(s_re, sg, bs, 8, 4);
        stage4p(s_im, sg, bs, 8, 4);
    }
    __syncthreads();

    // wire 5 (bit 12) RY + diagonal RZ + CNOT-ladder permutation
    int pm = (__popc(H) & 1) ? (CHUNK - 1) : 0;
    int Hd = H ^ (H >> 1); Hd ^= Hd >> 2; Hd ^= Hd >> 4;   // invgray5
    u64 c5 = sg[0][0], s5 = sg[0][1], ns5 = sg[0][2];

    if (!LAST) {
        long obase = (long)b * DIM + ((long)Hd << CHUNK_BITS);
        __half2* dre = ore + obase;
        __half2* dim = oim + obase;
#pragma unroll
        for (int k = 0; k < 4; ++k) {
            int t = 2 * (tid + k * PL_THREADS);     // even, [0,4096)
            int uu = t + 4096;
            u64 rt = h2u_pk(s_re[SWX(t)]),       it = h2u_pk(s_im[SWX(t)]);
            u64 rt1 = h2u_pk(s_re[SWX(t + 1)]),  it1 = h2u_pk(s_im[SWX(t + 1)]);
            u64 ru = h2u_pk(s_re[SWX(uu)]),      iu = h2u_pk(s_im[SWX(uu)]);
            u64 ru1 = h2u_pk(s_re[SWX(uu + 1)]), iu1 = h2u_pk(s_im[SWX(uu + 1)]);
            ry1(rt, ru, c5, s5, ns5);   ry1(it, iu, c5, s5, ns5);
            ry1(rt1, ru1, c5, s5, ns5); ry1(it1, iu1, c5, s5, ns5);
            float2 lo0 = Plo[t & 63], lo1 = Plo[(t & 63) | 1];
            float2 hT = Phi[t >> 6], hU = Phi[(t >> 6) + 64];
            capply(rt, it, cmulf(lo0, hT));   capply(rt1, it1, cmulf(lo1, hT));
            capply(ru, iu, cmulf(lo0, hU));   capply(ru1, iu1, cmulf(lo1, hU));
            int q = invgray(t) ^ pm;
            int qu = q ^ 8191;                      // invgray(4096)=8191
            st_pair(dre, q, rt, rt1);  st_pair(dim, q, it, it1);
            st_pair(dre, qu, ru, ru1); st_pair(dim, qu, iu, iu1);
        }
    } else {
        float a0[NUM_WIRES], a1[NUM_WIRES];
#pragma unroll
        for (int w = 0; w < NUM_WIRES; ++w) { a0[w] = 0.0f; a1[w] = 0.0f; }
        int hi = Hd << CHUNK_BITS;
#pragma unroll
        for (int k = 0; k < 4; ++k) {
            int t = 2 * (tid + k * PL_THREADS);
            int uu = t + 4096;
            u64 rt = h2u_pk(s_re[SWX(t)]),       it = h2u_pk(s_im[SWX(t)]);
            u64 rt1 = h2u_pk(s_re[SWX(t + 1)]),  it1 = h2u_pk(s_im[SWX(t + 1)]);
            u64 ru = h2u_pk(s_re[SWX(uu)]),      iu = h2u_pk(s_im[SWX(uu)]);
            u64 ru1 = h2u_pk(s_re[SWX(uu + 1)]), iu1 = h2u_pk(s_im[SWX(uu + 1)]);
            ry1(rt, ru, c5, s5, ns5);   ry1(it, iu, c5, s5, ns5);
            ry1(rt1, ru1, c5, s5, ns5); ry1(it1, iu1, c5, s5, ns5);
            int q = invgray(t) ^ pm;
            int qu = q ^ 8191;
            float2 pt  = up(fma2(rt, rt, mul2(it, it)));
            float2 pt1 = up(fma2(rt1, rt1, mul2(it1, it1)));
            float2 pu  = up(fma2(ru, ru, mul2(iu, iu)));
            float2 pu1 = up(fma2(ru1, ru1, mul2(iu1, iu1)));
            {
                int d = hi | q;
                unsigned bb0 = __float_as_uint(pt.x + pt1.x);
                unsigned bb1 = __float_as_uint(pt.y + pt1.y);
#pragma unroll
                for (int w = 0; w < 17; ++w) {
                    unsigned bit = (unsigned)(d >> (17 - w)) & 1u;
                    a0[w] += __uint_as_float(bb0 ^ (bit << 31));
                    a1[w] += __uint_as_float(bb1 ^ (bit << 31));
                }
                float d0 = pt.x - pt1.x, d1 = pt.y - pt1.y;
                a0[17] += (q & 1) ? -d0 : d0;
                a1[17] += (q & 1) ? -d1 : d1;
            }
            {
                int d = hi | qu;
                unsigned bb0 = __float_as_uint(pu.x + pu1.x);
                unsigned bb1 = __float_as_uint(pu.y + pu1.y);
#pragma unroll
                for (int w = 0; w < 17; ++w) {
                    unsigned bit = (unsigned)(d >> (17 - w)) & 1u;
                    a0[w] += __uint_as_float(bb0 ^ (bit << 31));
                    a1[w] += __uint_as_float(bb1 ^ (bit << 31));
                }
                float d0 = pu.x - pu1.x, d1 = pu.y - pu1.y;
                a0[17] += (qu & 1) ? -d0 : d0;
                a1[17] += (qu & 1) ? -d1 : d1;
            }
        }
#pragma unroll
        for (int w = 0; w < NUM_WIRES; ++w)
#pragma unroll
            for (int o = 16; o; o >>= 1) {
                a0[w] += __shfl_down_sync(0xFFFFFFFFu, a0[w], o);
                a1[w] += __shfl_down_sync(0xFFFFFFFFu, a1[w], o);
            }
        __syncthreads();
        float* scratch = (float*)smem_u;
        int warp = tid >> 5, lane = tid & 31;
        if (lane == 0) {
#pragma unroll
            for (int w = 0; w < NUM_WIRES; ++w) {
                scratch[(warp * 2 + 0) * NUM_WIRES + w] = a0[w];
                scratch[(warp * 2 + 1) * NUM_WIRES + w] = a1[w];
            }
        }
        __syncthreads();
        if (tid < 2 * NUM_WIRES) {
            int s = tid / NUM_WIRES, w = tid % NUM_WIRES;
            float sum = 0.0f;
#pragma unroll
            for (int k = 0; k < PL_THREADS / 32; ++k)
                sum += scratch[(k * 2 + s) * NUM_WIRES + w];
            partial[(((long)(2 * b + s)) * NCHUNK + H) * NUM_WIRES + w] = sum;
        }
    }
}

__global__ void k_head(const float* __restrict__ head_w,
                       const float* __restrict__ head_b,
                       float* __restrict__ out) {
    int b = threadIdx.x;
    if (b < BATCH) {
        float s = head_b[0];
#pragma unroll
        for (int w = 0; w < NUM_WIRES; ++w) {
            float f = 0.0f;
#pragma unroll
            for (int c = 0; c < NCHUNK; ++c)
                f += g_partial[((long)b * NCHUNK + c) * NUM_WIRES + w];
            s = fmaf(f, head_w[w], s);
        }
        out[b] = s;
    }
}

extern "C" void kernel_launch(void* const* d_in, const int* in_sizes, int n_in,
                              void* d_out, int out_size) {
    const float* state_re = (const float*)d_in[0];
    const float* state_im = (const float*)d_in[1];
    const float* params   = (const float*)d_in[2];
    const float* head_w   = (const float*)d_in[3];
    const float* head_b   = (const float*)d_in[4];
    float* out = (float*)d_out;

    const int shmem = 2 * CHUNK * (int)sizeof(unsigned);   // 64KB
    cudaFuncSetAttribute(k_pass_low<0>, cudaFuncAttributeMaxDynamicSharedMemorySize, shmem);
    cudaFuncSetAttribute(k_pass_low<1>, cudaFuncAttributeMaxDynamicSharedMemorySize, shmem);

    static __half2 *re0 = nullptr, *im0 = nullptr, *re1 = nullptr, *im1 = nullptr;
    static float* ptp = nullptr;
    if (!re0) {
        cudaGetSymbolAddress((void**)&re0, g_re0);
        cudaGetSymbolAddress((void**)&im0, g_im0);
        cudaGetSymbolAddress((void**)&re1, g_re1);
        cudaGetSymbolAddress((void**)&im1, g_im1);
        cudaGetSymbolAddress((void**)&ptp, g_partial);
    }

    const int ph_blocks = (GP * 2 * CHUNK) / PH_THREADS;   // 1024
    const int pl_blocks = GP * NCHUNK;                     // 512

    // L2-resident groups of GP=16 pairs (working set 67MB < L2)
    for (int grp = 0; grp < NPAIR / GP; ++grp) {
        long poff = (long)grp * GP * DIM;       // pair-plane offset
        long soff = (long)grp * GP * 2 * DIM;   // fp32 input offset
        __half2 *r0 = re0 + poff, *i0 = im0 + poff;
        __half2 *r1 = re1 + poff, *i1 = im1 + poff;
        float* part = ptp + (long)grp * GP * 2 * NCHUNK * NUM_WIRES;

        // layer 0
        k_first<<<ph_blocks, PH_THREADS>>>(state_re + soff, state_im + soff, r0, i0, params);
        k_pass_low<0><<<pl_blocks, PL_THREADS, shmem>>>(r0, i0, r1, i1, params, part, 0);
        // layer 1
        k_pass_high<<<ph_blocks, PH_THREADS>>>(r1, i1, params, 1);
        k_pass_low<0><<<pl_blocks, PL_THREADS, shmem>>>(r1, i1, r0, i0, params, part, 1);
        // layer 2
        k_pass_high<<<ph_blocks, PH_THREADS>>>(r0, i0, params, 2);
        k_pass_low<1><<<pl_blocks, PL_THREADS, shmem>>>(r0, i0, r1, i1, params, part, 2);
    }

    k_head<<<1, 64>>>(head_w, head_b, out);
}